// round 1
// baseline (speedup 1.0000x reference)
#include <cuda_runtime.h>
#include <math.h>

#define NN 100000
#define EE 1600000
#define DD 128
#define HH 4

// ---------------- device scratch (static globals: allocation-free rule) ----
__device__ float g_x1[(size_t)NN * DD];     // after linear1
__device__ float g_h[(size_t)NN * DD];      // after GAT lin
__device__ float g_agg[(size_t)NN * DD];    // aggregated messages
__device__ float g_asrc[NN * HH];
__device__ float g_adst[NN * HH];
__device__ float g_denom[NN * HH];
__device__ float g_ex[(size_t)EE * HH];

__device__ __forceinline__ float lrelu(float x, float s) {
    return x >= 0.f ? x : s * x;
}

// vector L2 reduction (sm_90+): 4 contiguous fp32 adds in one L2 atomic op
__device__ __forceinline__ void red4(float* addr, float4 v) {
    asm volatile("red.global.add.v4.f32 [%0], {%1,%2,%3,%4};"
                 :: "l"(addr), "f"(v.x), "f"(v.y), "f"(v.z), "f"(v.w)
                 : "memory");
}

// ---------------------------------------------------------------------------
// GEMM: out[M,128] = act(A + prebias) @ W^T + bias
//   A: [M,128] row-major, W: [128,128] row-major (out_j = sum_k A_k * W[j][k])
// Block tile 128x128, K=128 fully resident in smem (128 KB dynamic).
// Smem layout: per 128-float row, 32 float4 cells, cell c stored at (c ^ (r&31))
// -> conflict-free float4 staging AND conflict-free compute reads.
// 256 threads, 8x8 micro-tile per thread: 16 FFMA per LDS.128.
// ---------------------------------------------------------------------------
template <bool ACT_IN>
__global__ void __launch_bounds__(256, 1) gemm_kernel(
    const float* __restrict__ A, const float* __restrict__ W,
    const float* __restrict__ prebias, const float* __restrict__ bias,
    float* __restrict__ out, int M)
{
    extern __shared__ float4 smem4[];
    float4* As4 = smem4;             // 128 rows x 32 cells
    float4* Bs4 = smem4 + 128 * 32;  // 128 rows x 32 cells

    const int tid = threadIdx.x;
    const int rowBase = blockIdx.x * 128;

    // stage A tile (with optional prebias + leaky(0.01) pre-activation)
#pragma unroll
    for (int i = 0; i < 16; i++) {
        int idx = tid + i * 256;    // 0..4095
        int r = idx >> 5;           // tile row 0..127
        int c = idx & 31;           // float4 cell 0..31
        int row = rowBase + r;
        float4 v = make_float4(0.f, 0.f, 0.f, 0.f);
        if (row < M) v = *(const float4*)(A + (size_t)row * DD + c * 4);
        if (prebias != nullptr) {
            float4 pb = *(const float4*)(prebias + c * 4);
            v.x += pb.x; v.y += pb.y; v.z += pb.z; v.w += pb.w;
        }
        if (ACT_IN) {
            v.x = lrelu(v.x, 0.01f); v.y = lrelu(v.y, 0.01f);
            v.z = lrelu(v.z, 0.01f); v.w = lrelu(v.w, 0.01f);
        }
        As4[r * 32 + (c ^ (r & 31))] = v;
    }
    // stage W tile
#pragma unroll
    for (int i = 0; i < 16; i++) {
        int idx = tid + i * 256;
        int r = idx >> 5;
        int c = idx & 31;
        float4 v = *(const float4*)(W + (size_t)r * DD + c * 4);
        Bs4[r * 32 + (c ^ (r & 31))] = v;
    }
    __syncthreads();

    const int tx = tid & 15, ty = tid >> 4;
    const int tm = ty * 8, tn = tx * 8;

    float acc[8][8];
#pragma unroll
    for (int i = 0; i < 8; i++)
#pragma unroll
        for (int j = 0; j < 8; j++) acc[i][j] = 0.f;

#pragma unroll 1
    for (int k4 = 0; k4 < 32; k4++) {
        float4 a4[8], b4[8];
#pragma unroll
        for (int i = 0; i < 8; i++)
            a4[i] = As4[(tm + i) * 32 + (k4 ^ ((tm + i) & 31))];
#pragma unroll
        for (int j = 0; j < 8; j++)
            b4[j] = Bs4[(tn + j) * 32 + (k4 ^ ((tn + j) & 31))];
#pragma unroll
        for (int i = 0; i < 8; i++)
#pragma unroll
            for (int j = 0; j < 8; j++) {
                acc[i][j] = fmaf(a4[i].x, b4[j].x, acc[i][j]);
                acc[i][j] = fmaf(a4[i].y, b4[j].y, acc[i][j]);
                acc[i][j] = fmaf(a4[i].z, b4[j].z, acc[i][j]);
                acc[i][j] = fmaf(a4[i].w, b4[j].w, acc[i][j]);
            }
    }

    float bj[8];
#pragma unroll
    for (int j = 0; j < 8; j++) bj[j] = (bias != nullptr) ? bias[tn + j] : 0.f;
#pragma unroll
    for (int i = 0; i < 8; i++) {
        int row = rowBase + tm + i;
        if (row < M) {
            float4 o0 = make_float4(acc[i][0] + bj[0], acc[i][1] + bj[1],
                                    acc[i][2] + bj[2], acc[i][3] + bj[3]);
            float4 o1 = make_float4(acc[i][4] + bj[4], acc[i][5] + bj[5],
                                    acc[i][6] + bj[6], acc[i][7] + bj[7]);
            *(float4*)(out + (size_t)row * DD + tn) = o0;
            *(float4*)(out + (size_t)row * DD + tn + 4) = o1;
        }
    }
}

// a_src[n,h] = sum_c h[n,h,c]*att_src[h,c]; heads map 1:1 onto warps (C=32)
__global__ void __launch_bounds__(128) attn_score_kernel(
    const float* __restrict__ att_src, const float* __restrict__ att_dst)
{
    int n = blockIdx.x;
    int c = threadIdx.x;  // channel 0..127
    float v = g_h[(size_t)n * DD + c];
    float s = v * att_src[c];
    float d = v * att_dst[c];
#pragma unroll
    for (int off = 16; off; off >>= 1) {
        s += __shfl_xor_sync(0xffffffffu, s, off);
        d += __shfl_xor_sync(0xffffffffu, d, off);
    }
    if ((c & 31) == 0) {
        g_asrc[n * HH + (c >> 5)] = s;
        g_adst[n * HH + (c >> 5)] = d;
    }
}

__global__ void zero_kernel() {
    const int AGG4 = NN * DD / 4;  // 3,200,000
    const int DEN4 = NN * HH / 4;  // 100,000
    int idx = blockIdx.x * blockDim.x + threadIdx.x;
    if (idx < AGG4)
        ((float4*)g_agg)[idx] = make_float4(0.f, 0.f, 0.f, 0.f);
    else if (idx < AGG4 + DEN4)
        ((float4*)g_denom)[idx - AGG4] = make_float4(0.f, 0.f, 0.f, 0.f);
}

// edge pass 1: ex = exp(leaky_0.2(a_src[src]+a_dst[dst])); denom[dst] += ex
// (segment-max skipped: softmax is shift-invariant and |alpha| <~ 3 here)
__global__ void __launch_bounds__(256) edge_pass1(const int* __restrict__ ei) {
    int e = blockIdx.x * blockDim.x + threadIdx.x;
    if (e >= EE) return;
    int src = ei[e];
    int dst = ei[EE + e];
    float4 s = *(const float4*)(g_asrc + src * 4);
    float4 d = *(const float4*)(g_adst + dst * 4);
    float4 ex;
    ex.x = expf(lrelu(s.x + d.x, 0.2f));
    ex.y = expf(lrelu(s.y + d.y, 0.2f));
    ex.z = expf(lrelu(s.z + d.z, 0.2f));
    ex.w = expf(lrelu(s.w + d.w, 0.2f));
    *(float4*)(g_ex + (size_t)e * 4) = ex;
    red4(g_denom + dst * 4, ex);
}

// edge pass 2: warp per edge; lane owns 4 contiguous channels (head = lane/8)
__global__ void __launch_bounds__(256) edge_pass2(const int* __restrict__ ei) {
    int gt = blockIdx.x * blockDim.x + threadIdx.x;
    int e = gt >> 5;
    int lane = gt & 31;
    if (e >= EE) return;
    int src = ei[e];
    int dst = ei[EE + e];
    int head = lane >> 3;
    float ex = g_ex[(size_t)e * 4 + head];
    float dn = g_denom[dst * 4 + head];
    float coeff = ex / (dn + 1e-16f);
    float4 hv = *(const float4*)(g_h + (size_t)src * DD + lane * 4);
    red4(g_agg + (size_t)dst * DD + lane * 4,
         make_float4(hv.x * coeff, hv.y * coeff, hv.z * coeff, hv.w * coeff));
}

// ---------------------------------------------------------------------------
extern "C" void kernel_launch(void* const* d_in, const int* in_sizes, int n_in,
                              void* d_out, int out_size) {
    const float* x       = (const float*)d_in[0];
    const int*   ei      = (const int*)d_in[1];
    // d_in[2] = edge_type (unused by forward)
    const float* W1      = (const float*)d_in[3];
    const float* b1      = (const float*)d_in[4];
    const float* Wg      = (const float*)d_in[5];
    const float* att_src = (const float*)d_in[6];
    const float* att_dst = (const float*)d_in[7];
    const float* bias_g  = (const float*)d_in[8];
    const float* W2      = (const float*)d_in[9];
    const float* b2      = (const float*)d_in[10];
    float* out = (float*)d_out;

    float *px1, *ph, *pagg;
    cudaGetSymbolAddress((void**)&px1, g_x1);
    cudaGetSymbolAddress((void**)&ph, g_h);
    cudaGetSymbolAddress((void**)&pagg, g_agg);

    const int SMEM = 2 * 128 * 128 * 4;  // 128 KB dynamic
    cudaFuncSetAttribute(gemm_kernel<true>,
                         cudaFuncAttributeMaxDynamicSharedMemorySize, SMEM);
    cudaFuncSetAttribute(gemm_kernel<false>,
                         cudaFuncAttributeMaxDynamicSharedMemorySize, SMEM);

    const int gblocks = (NN + 127) / 128;  // 782

    // x1 = leaky(x,0.01) @ W1^T + b1
    gemm_kernel<true><<<gblocks, 256, SMEM>>>(x, W1, nullptr, b1, px1, NN);
    // h = x1 @ Wg^T
    gemm_kernel<false><<<gblocks, 256, SMEM>>>(px1, Wg, nullptr, nullptr, ph, NN);
    // per-node attention scores
    attn_score_kernel<<<NN, 128>>>(att_src, att_dst);
    // zero accumulators (denom + agg)
    {
        const int z4 = NN * DD / 4 + NN * HH / 4;
        zero_kernel<<<(z4 + 255) / 256, 256>>>();
    }
    // softmax numerator + denominator
    edge_pass1<<<(EE + 255) / 256, 256>>>(ei);
    // weighted message aggregation (warp per edge)
    edge_pass2<<<(int)(((long long)EE * 32 + 255) / 256), 256>>>(ei);
    // out = leaky(agg + bias_g, 0.01) @ W2^T + b2
    gemm_kernel<true><<<gblocks, 256, SMEM>>>(pagg, W2, bias_g, b2, out, NN);
}

// round 2
// speedup vs baseline: 1.0547x; 1.0547x over previous
#include <cuda_runtime.h>
#include <math.h>

#define NN 100000
#define EE 1600000
#define DD 128
#define HH 4

// ---------------- device scratch (static globals: allocation-free rule) ----
__device__ float g_x1[(size_t)NN * DD];     // after linear1
__device__ float g_h[(size_t)NN * DD];      // after GAT lin
__device__ float g_agg[(size_t)NN * DD];    // aggregated messages
__device__ float g_asrc[NN * HH];
__device__ float g_adst[NN * HH];
__device__ int   g_cnt[NN];                 // per-dst degree
__device__ int   g_off[NN + 1];             // CSR offsets
__device__ int   g_cur[NN];                 // scatter cursors
__device__ int   g_csr_src[EE];             // src node per edge, bucketed by dst

__device__ __forceinline__ float lrelu(float x, float s) {
    return x >= 0.f ? x : s * x;
}

// ---------------------------------------------------------------------------
// GEMM: out[M,128] = act(A + prebias) @ W^T + bias   (fp32 FFMA, 128^3 tile)
// ---------------------------------------------------------------------------
template <bool ACT_IN>
__global__ void __launch_bounds__(256, 1) gemm_kernel(
    const float* __restrict__ A, const float* __restrict__ W,
    const float* __restrict__ prebias, const float* __restrict__ bias,
    float* __restrict__ out, int M)
{
    extern __shared__ float4 smem4[];
    float4* As4 = smem4;             // 128 rows x 32 cells
    float4* Bs4 = smem4 + 128 * 32;  // 128 rows x 32 cells

    const int tid = threadIdx.x;
    const int rowBase = blockIdx.x * 128;

#pragma unroll
    for (int i = 0; i < 16; i++) {
        int idx = tid + i * 256;
        int r = idx >> 5;
        int c = idx & 31;
        int row = rowBase + r;
        float4 v = make_float4(0.f, 0.f, 0.f, 0.f);
        if (row < M) v = *(const float4*)(A + (size_t)row * DD + c * 4);
        if (prebias != nullptr) {
            float4 pb = *(const float4*)(prebias + c * 4);
            v.x += pb.x; v.y += pb.y; v.z += pb.z; v.w += pb.w;
        }
        if (ACT_IN) {
            v.x = lrelu(v.x, 0.01f); v.y = lrelu(v.y, 0.01f);
            v.z = lrelu(v.z, 0.01f); v.w = lrelu(v.w, 0.01f);
        }
        As4[r * 32 + (c ^ (r & 31))] = v;
    }
#pragma unroll
    for (int i = 0; i < 16; i++) {
        int idx = tid + i * 256;
        int r = idx >> 5;
        int c = idx & 31;
        float4 v = *(const float4*)(W + (size_t)r * DD + c * 4);
        Bs4[r * 32 + (c ^ (r & 31))] = v;
    }
    __syncthreads();

    const int tx = tid & 15, ty = tid >> 4;
    const int tm = ty * 8, tn = tx * 8;

    float acc[8][8];
#pragma unroll
    for (int i = 0; i < 8; i++)
#pragma unroll
        for (int j = 0; j < 8; j++) acc[i][j] = 0.f;

#pragma unroll 1
    for (int k4 = 0; k4 < 32; k4++) {
        float4 a4[8], b4[8];
#pragma unroll
        for (int i = 0; i < 8; i++)
            a4[i] = As4[(tm + i) * 32 + (k4 ^ ((tm + i) & 31))];
#pragma unroll
        for (int j = 0; j < 8; j++)
            b4[j] = Bs4[(tn + j) * 32 + (k4 ^ ((tn + j) & 31))];
#pragma unroll
        for (int i = 0; i < 8; i++)
#pragma unroll
            for (int j = 0; j < 8; j++) {
                acc[i][j] = fmaf(a4[i].x, b4[j].x, acc[i][j]);
                acc[i][j] = fmaf(a4[i].y, b4[j].y, acc[i][j]);
                acc[i][j] = fmaf(a4[i].z, b4[j].z, acc[i][j]);
                acc[i][j] = fmaf(a4[i].w, b4[j].w, acc[i][j]);
            }
    }

    float bj[8];
#pragma unroll
    for (int j = 0; j < 8; j++) bj[j] = (bias != nullptr) ? bias[tn + j] : 0.f;
#pragma unroll
    for (int i = 0; i < 8; i++) {
        int row = rowBase + tm + i;
        if (row < M) {
            float4 o0 = make_float4(acc[i][0] + bj[0], acc[i][1] + bj[1],
                                    acc[i][2] + bj[2], acc[i][3] + bj[3]);
            float4 o1 = make_float4(acc[i][4] + bj[4], acc[i][5] + bj[5],
                                    acc[i][6] + bj[6], acc[i][7] + bj[7]);
            *(float4*)(out + (size_t)row * DD + tn) = o0;
            *(float4*)(out + (size_t)row * DD + tn + 4) = o1;
        }
    }
}

// a_src[n,h] = sum_c h[n,h,c]*att_src[h,c]
__global__ void __launch_bounds__(128) attn_score_kernel(
    const float* __restrict__ att_src, const float* __restrict__ att_dst)
{
    int n = blockIdx.x;
    int c = threadIdx.x;
    float v = g_h[(size_t)n * DD + c];
    float s = v * att_src[c];
    float d = v * att_dst[c];
#pragma unroll
    for (int off = 16; off; off >>= 1) {
        s += __shfl_xor_sync(0xffffffffu, s, off);
        d += __shfl_xor_sync(0xffffffffu, d, off);
    }
    if ((c & 31) == 0) {
        g_asrc[n * HH + (c >> 5)] = s;
        g_adst[n * HH + (c >> 5)] = d;
    }
}

// -------------------------- CSR construction ------------------------------
__global__ void __launch_bounds__(256) hist_kernel(const int* __restrict__ ei) {
    int e = blockIdx.x * blockDim.x + threadIdx.x;
    if (e >= EE) return;
    atomicAdd(&g_cnt[ei[EE + e]], 1);
}

// single-block exclusive scan of g_cnt -> g_off (+ cursor copy)
__global__ void __launch_bounds__(1024) scan_kernel() {
    __shared__ int ssum[1024];
    const int t = threadIdx.x;
    const int CH = (NN + 1023) / 1024;  // 98
    const int base = t * CH;

    int s = 0;
#pragma unroll 4
    for (int i = 0; i < CH; i++) {
        int idx = base + i;
        if (idx < NN) s += g_cnt[idx];
    }
    ssum[t] = s;
    __syncthreads();
    // Hillis-Steele inclusive scan
    for (int off = 1; off < 1024; off <<= 1) {
        int v = ssum[t];
        int add = (t >= off) ? ssum[t - off] : 0;
        __syncthreads();
        ssum[t] = v + add;
        __syncthreads();
    }
    int run = ssum[t] - s;  // exclusive prefix of this thread's chunk
    for (int i = 0; i < CH; i++) {
        int idx = base + i;
        if (idx < NN) {
            g_off[idx] = run;
            g_cur[idx] = run;
            run += g_cnt[idx];
        }
    }
    if (t == 1023) g_off[NN] = EE;
}

__global__ void __launch_bounds__(256) scatter_kernel(const int* __restrict__ ei) {
    int e = blockIdx.x * blockDim.x + threadIdx.x;
    if (e >= EE) return;
    int src = ei[e];
    int dst = ei[EE + e];
    int pos = atomicAdd(&g_cur[dst], 1);
    g_csr_src[pos] = src;
}

// ---------------------------------------------------------------------------
// Fused softmax + aggregation: warp per dst node.
//   out[d] = sum_e ex_e * h[src_e] / (sum_e ex_e + 1e-16)
// Each lane owns 4 contiguous channels; head = lane>>3.
// ---------------------------------------------------------------------------
__global__ void __launch_bounds__(256) agg_kernel() {
    int warp = (blockIdx.x * blockDim.x + threadIdx.x) >> 5;
    int lane = threadIdx.x & 31;
    if (warp >= NN) return;
    const int d = warp;
    const int head = lane >> 3;

    const float adst = g_adst[d * HH + head];
    const int beg = g_off[d];
    const int end = g_off[d + 1];

    float4 acc = make_float4(0.f, 0.f, 0.f, 0.f);
    float den = 0.f;

#pragma unroll 2
    for (int i = beg; i < end; i++) {
        int src = g_csr_src[i];                       // warp-uniform load
        float s = g_asrc[src * HH + head] + adst;     // 8-way broadcast
        float ex = expf(lrelu(s, 0.2f));
        float4 hv = *(const float4*)(g_h + (size_t)src * DD + lane * 4);
        acc.x = fmaf(ex, hv.x, acc.x);
        acc.y = fmaf(ex, hv.y, acc.y);
        acc.z = fmaf(ex, hv.z, acc.z);
        acc.w = fmaf(ex, hv.w, acc.w);
        den += ex;
    }
    float inv = 1.f / (den + 1e-16f);
    acc.x *= inv; acc.y *= inv; acc.z *= inv; acc.w *= inv;
    *(float4*)(g_agg + (size_t)d * DD + lane * 4) = acc;
}

// ---------------------------------------------------------------------------
extern "C" void kernel_launch(void* const* d_in, const int* in_sizes, int n_in,
                              void* d_out, int out_size) {
    const float* x       = (const float*)d_in[0];
    const int*   ei      = (const int*)d_in[1];
    // d_in[2] = edge_type (unused by forward)
    const float* W1      = (const float*)d_in[3];
    const float* b1      = (const float*)d_in[4];
    const float* Wg      = (const float*)d_in[5];
    const float* att_src = (const float*)d_in[6];
    const float* att_dst = (const float*)d_in[7];
    const float* bias_g  = (const float*)d_in[8];
    const float* W2      = (const float*)d_in[9];
    const float* b2      = (const float*)d_in[10];
    float* out = (float*)d_out;

    float *px1, *ph, *pagg;
    int *pcnt;
    cudaGetSymbolAddress((void**)&px1, g_x1);
    cudaGetSymbolAddress((void**)&ph, g_h);
    cudaGetSymbolAddress((void**)&pagg, g_agg);
    cudaGetSymbolAddress((void**)&pcnt, g_cnt);

    const int SMEM = 2 * 128 * 128 * 4;  // 128 KB dynamic
    cudaFuncSetAttribute(gemm_kernel<true>,
                         cudaFuncAttributeMaxDynamicSharedMemorySize, SMEM);
    cudaFuncSetAttribute(gemm_kernel<false>,
                         cudaFuncAttributeMaxDynamicSharedMemorySize, SMEM);

    const int gblocks = (NN + 127) / 128;  // 782

    // x1 = leaky(x,0.01) @ W1^T + b1
    gemm_kernel<true><<<gblocks, 256, SMEM>>>(x, W1, nullptr, b1, px1, NN);
    // h = x1 @ Wg^T
    gemm_kernel<false><<<gblocks, 256, SMEM>>>(px1, Wg, nullptr, nullptr, ph, NN);
    // per-node attention scores
    attn_score_kernel<<<NN, 128>>>(att_src, att_dst);

    // CSR build (per call; graph-capturable, no allocs)
    cudaMemsetAsync(pcnt, 0, NN * sizeof(int));
    hist_kernel<<<(EE + 255) / 256, 256>>>(ei);
    scan_kernel<<<1, 1024>>>();
    scatter_kernel<<<(EE + 255) / 256, 256>>>(ei);

    // fused softmax + message aggregation (warp per dst)
    agg_kernel<<<(NN * 32 + 255) / 256, 256>>>();

    // out = leaky(agg + bias_g, 0.01) @ W2^T + b2
    gemm_kernel<true><<<gblocks, 256, SMEM>>>(pagg, W2, bias_g, b2, out, NN);
}

// round 4
// speedup vs baseline: 1.3099x; 1.2420x over previous
#include <cuda_runtime.h>
#include <math.h>

#define NN 100000
#define EE 1600000
#define DD 128
#define HH 4

// ---------------- device scratch (static globals: allocation-free rule) ----
__device__ float g_h[(size_t)NN * DD];      // after fused linear1+GAT lin
__device__ float g_agg[(size_t)NN * DD];    // aggregated messages
__device__ float g_Wf[DD * DD];             // Wg @ W1
__device__ float g_bf[DD];                  // Wg @ b1
__device__ float g_asrc[NN * HH];
__device__ float g_adst[NN * HH];
__device__ int   g_cnt[NN];                 // per-dst degree
__device__ int   g_off[NN + 1];             // CSR offsets
__device__ int   g_cur[NN];                 // scatter cursors
__device__ int   g_csr_src[EE];             // src node per edge, bucketed by dst

__device__ __forceinline__ float lrelu(float x, float s) {
    return x >= 0.f ? x : s * x;
}

// ---------------------------------------------------------------------------
// Weight fusion: Wf[i,k] = sum_j Wg[i,j] * W1[j,k];  bf[i] = sum_j Wg[i,j]*b1[j]
// Block i computes row i (128 threads, thread k owns column k).
// ---------------------------------------------------------------------------
__global__ void __launch_bounds__(128) wf_kernel(
    const float* __restrict__ Wg, const float* __restrict__ W1,
    const float* __restrict__ b1)
{
    const int i = blockIdx.x;
    const int k = threadIdx.x;
    float acc = 0.f;
    float accb = 0.f;
#pragma unroll 8
    for (int j = 0; j < DD; j++) {
        float w = Wg[i * DD + j];
        acc = fmaf(w, W1[j * DD + k], acc);
        accb = fmaf(w, b1[j], accb);
    }
    g_Wf[i * DD + k] = acc;
    if (k == 0) {
        // recompute bf fully in lane 0? accb above is partial per-thread; fix:
    }
    // bf: reduce accb across the block is overkill; do it directly:
    // each thread computed sum_j Wg[i,j]*b1[j] identically? No - accb is the
    // full sum already (loop over all j in every thread). Write once.
    if (k == 0) g_bf[i] = accb;
}

// ---------------------------------------------------------------------------
// GEMM: out[M,128] = act(A + prebias) @ W^T + bias   (fp32 FFMA, 128^3 tile)
// ---------------------------------------------------------------------------
template <bool ACT_IN>
__global__ void __launch_bounds__(256, 1) gemm_kernel(
    const float* __restrict__ A, const float* __restrict__ W,
    const float* __restrict__ prebias, const float* __restrict__ bias,
    float* __restrict__ out, int M)
{
    extern __shared__ float4 smem4[];
    float4* As4 = smem4;             // 128 rows x 32 cells
    float4* Bs4 = smem4 + 128 * 32;  // 128 rows x 32 cells

    const int tid = threadIdx.x;
    const int rowBase = blockIdx.x * 128;

#pragma unroll
    for (int i = 0; i < 16; i++) {
        int idx = tid + i * 256;
        int r = idx >> 5;
        int c = idx & 31;
        int row = rowBase + r;
        float4 v = make_float4(0.f, 0.f, 0.f, 0.f);
        if (row < M) v = *(const float4*)(A + (size_t)row * DD + c * 4);
        if (prebias != nullptr) {
            float4 pb = *(const float4*)(prebias + c * 4);
            v.x += pb.x; v.y += pb.y; v.z += pb.z; v.w += pb.w;
        }
        if (ACT_IN) {
            v.x = lrelu(v.x, 0.01f); v.y = lrelu(v.y, 0.01f);
            v.z = lrelu(v.z, 0.01f); v.w = lrelu(v.w, 0.01f);
        }
        As4[r * 32 + (c ^ (r & 31))] = v;
    }
#pragma unroll
    for (int i = 0; i < 16; i++) {
        int idx = tid + i * 256;
        int r = idx >> 5;
        int c = idx & 31;
        float4 v = *(const float4*)(W + (size_t)r * DD + c * 4);
        Bs4[r * 32 + (c ^ (r & 31))] = v;
    }
    __syncthreads();

    const int tx = tid & 15, ty = tid >> 4;
    const int tm = ty * 8, tn = tx * 8;

    float acc[8][8];
#pragma unroll
    for (int i = 0; i < 8; i++)
#pragma unroll
        for (int j = 0; j < 8; j++) acc[i][j] = 0.f;

#pragma unroll 1
    for (int k4 = 0; k4 < 32; k4++) {
        float4 a4[8], b4[8];
#pragma unroll
        for (int i = 0; i < 8; i++)
            a4[i] = As4[(tm + i) * 32 + (k4 ^ ((tm + i) & 31))];
#pragma unroll
        for (int j = 0; j < 8; j++)
            b4[j] = Bs4[(tn + j) * 32 + (k4 ^ ((tn + j) & 31))];
#pragma unroll
        for (int i = 0; i < 8; i++)
#pragma unroll
            for (int j = 0; j < 8; j++) {
                acc[i][j] = fmaf(a4[i].x, b4[j].x, acc[i][j]);
                acc[i][j] = fmaf(a4[i].y, b4[j].y, acc[i][j]);
                acc[i][j] = fmaf(a4[i].z, b4[j].z, acc[i][j]);
                acc[i][j] = fmaf(a4[i].w, b4[j].w, acc[i][j]);
            }
    }

    float bj[8];
#pragma unroll
    for (int j = 0; j < 8; j++) bj[j] = (bias != nullptr) ? bias[tn + j] : 0.f;
#pragma unroll
    for (int i = 0; i < 8; i++) {
        int row = rowBase + tm + i;
        if (row < M) {
            float4 o0 = make_float4(acc[i][0] + bj[0], acc[i][1] + bj[1],
                                    acc[i][2] + bj[2], acc[i][3] + bj[3]);
            float4 o1 = make_float4(acc[i][4] + bj[4], acc[i][5] + bj[5],
                                    acc[i][6] + bj[6], acc[i][7] + bj[7]);
            *(float4*)(out + (size_t)row * DD + tn) = o0;
            *(float4*)(out + (size_t)row * DD + tn + 4) = o1;
        }
    }
}

// a_src[n,h] = sum_c h[n,h,c]*att_src[h,c]
__global__ void __launch_bounds__(128) attn_score_kernel(
    const float* __restrict__ att_src, const float* __restrict__ att_dst)
{
    int n = blockIdx.x;
    int c = threadIdx.x;
    float v = g_h[(size_t)n * DD + c];
    float s = v * att_src[c];
    float d = v * att_dst[c];
#pragma unroll
    for (int off = 16; off; off >>= 1) {
        s += __shfl_xor_sync(0xffffffffu, s, off);
        d += __shfl_xor_sync(0xffffffffu, d, off);
    }
    if ((c & 31) == 0) {
        g_asrc[n * HH + (c >> 5)] = s;
        g_adst[n * HH + (c >> 5)] = d;
    }
}

// -------------------------- CSR construction ------------------------------
__global__ void __launch_bounds__(256) hist_kernel(const int* __restrict__ ei) {
    int e = blockIdx.x * blockDim.x + threadIdx.x;
    if (e >= EE) return;
    atomicAdd(&g_cnt[ei[EE + e]], 1);
}

__global__ void __launch_bounds__(1024) scan_kernel() {
    __shared__ int ssum[1024];
    const int t = threadIdx.x;
    const int CH = (NN + 1023) / 1024;  // 98
    const int base = t * CH;

    int s = 0;
#pragma unroll 4
    for (int i = 0; i < CH; i++) {
        int idx = base + i;
        if (idx < NN) s += g_cnt[idx];
    }
    ssum[t] = s;
    __syncthreads();
    for (int off = 1; off < 1024; off <<= 1) {
        int v = ssum[t];
        int add = (t >= off) ? ssum[t - off] : 0;
        __syncthreads();
        ssum[t] = v + add;
        __syncthreads();
    }
    int run = ssum[t] - s;
    for (int i = 0; i < CH; i++) {
        int idx = base + i;
        if (idx < NN) {
            g_off[idx] = run;
            g_cur[idx] = run;
            run += g_cnt[idx];
        }
    }
    if (t == 1023) g_off[NN] = EE;
}

__global__ void __launch_bounds__(256) scatter_kernel(const int* __restrict__ ei) {
    int e = blockIdx.x * blockDim.x + threadIdx.x;
    if (e >= EE) return;
    int src = ei[e];
    int dst = ei[EE + e];
    int pos = atomicAdd(&g_cur[dst], 1);
    g_csr_src[pos] = src;
}

// ---------------------------------------------------------------------------
// Fused softmax + aggregation: warp per dst. Edge-parallel prefetch:
// lane = edge_slot*4 + head loads src + computes exp once per (edge, head);
// inner loop shuffles (src, ex) and issues 8 independent float4 gathers.
// ---------------------------------------------------------------------------
__global__ void __launch_bounds__(256) agg_kernel() {
    int warp = (blockIdx.x * blockDim.x + threadIdx.x) >> 5;
    int lane = threadIdx.x & 31;
    if (warp >= NN) return;
    const int d = warp;
    const int head = lane >> 3;     // consumer head (channel group)
    const int ph = lane & 3;        // producer head
    const int pe = lane >> 2;       // producer edge slot 0..7
    const int beg = g_off[d], end = g_off[d + 1];
    const float adst_ph = g_adst[d * HH + ph];

    float4 acc = make_float4(0.f, 0.f, 0.f, 0.f);
    float den = 0.f;

    for (int base = beg; base < end; base += 8) {
        int eidx = base + pe;
        int srcl = 0;
        float exv = 0.f;
        if (eidx < end) {
            srcl = g_csr_src[eidx];
            float s = g_asrc[srcl * HH + ph] + adst_ph;
            exv = expf(lrelu(s, 0.2f));
        }
#pragma unroll
        for (int j = 0; j < 8; j++) {
            float ex = __shfl_sync(0xffffffffu, exv, j * 4 + head);
            int s = __shfl_sync(0xffffffffu, srcl, j * 4 + head);
            if (ex != 0.f) {
                float4 hv = *(const float4*)(g_h + (size_t)s * DD + lane * 4);
                acc.x = fmaf(ex, hv.x, acc.x);
                acc.y = fmaf(ex, hv.y, acc.y);
                acc.z = fmaf(ex, hv.z, acc.z);
                acc.w = fmaf(ex, hv.w, acc.w);
                den += ex;
            }
        }
    }
    float inv = 1.f / (den + 1e-16f);
    *(float4*)(g_agg + (size_t)d * DD + lane * 4) =
        make_float4(acc.x * inv, acc.y * inv, acc.z * inv, acc.w * inv);
}

// ---------------------------------------------------------------------------
extern "C" void kernel_launch(void* const* d_in, const int* in_sizes, int n_in,
                              void* d_out, int out_size) {
    const float* x       = (const float*)d_in[0];
    const int*   ei      = (const int*)d_in[1];
    // d_in[2] = edge_type (unused by forward)
    const float* W1      = (const float*)d_in[3];
    const float* b1      = (const float*)d_in[4];
    const float* Wg      = (const float*)d_in[5];
    const float* att_src = (const float*)d_in[6];
    const float* att_dst = (const float*)d_in[7];
    const float* bias_g  = (const float*)d_in[8];
    const float* W2      = (const float*)d_in[9];
    const float* b2      = (const float*)d_in[10];
    float* out = (float*)d_out;

    float *ph, *pagg, *pWf, *pbf;
    int *pcnt;
    cudaGetSymbolAddress((void**)&ph, g_h);
    cudaGetSymbolAddress((void**)&pagg, g_agg);
    cudaGetSymbolAddress((void**)&pWf, g_Wf);
    cudaGetSymbolAddress((void**)&pbf, g_bf);
    cudaGetSymbolAddress((void**)&pcnt, g_cnt);

    const int SMEM = 2 * 128 * 128 * 4;  // 128 KB dynamic
    cudaFuncSetAttribute(gemm_kernel<true>,
                         cudaFuncAttributeMaxDynamicSharedMemorySize, SMEM);

    const int gblocks = (NN + 127) / 128;  // 782

    // Wf = Wg @ W1, bf = Wg @ b1 (tiny)
    wf_kernel<<<DD, DD>>>(Wg, W1, b1);
    // h = leaky(x,0.01) @ Wf^T + bf   (fused linear1 + GAT lin)
    gemm_kernel<true><<<gblocks, 256, SMEM>>>(x, pWf, nullptr, pbf, ph, NN);
    // per-node attention scores
    attn_score_kernel<<<NN, 128>>>(att_src, att_dst);

    // CSR build (per call; graph-capturable, no allocs)
    cudaMemsetAsync(pcnt, 0, NN * sizeof(int));
    hist_kernel<<<(EE + 255) / 256, 256>>>(ei);
    scan_kernel<<<1, 1024>>>();
    scatter_kernel<<<(EE + 255) / 256, 256>>>(ei);

    // fused softmax + message aggregation (warp per dst)
    agg_kernel<<<(NN * 32 + 255) / 256, 256>>>();

    // out = leaky(agg + bias_g, 0.01) @ W2^T + b2
    gemm_kernel<true><<<gblocks, 256, SMEM>>>(pagg, W2, bias_g, b2, out, NN);
}

// round 5
// speedup vs baseline: 1.3969x; 1.0664x over previous
#include <cuda_runtime.h>
#include <math.h>

#define NN 100000
#define EE 1600000
#define DD 128
#define HH 4

// ---------------- device scratch (static globals: allocation-free rule) ----
__device__ float g_h[(size_t)NN * DD];      // after fused linear1+GAT lin
__device__ float g_agg[(size_t)NN * DD];    // aggregated messages
__device__ float g_Wf[DD * DD];             // Wg @ W1
__device__ float g_bf[DD];                  // Wg @ b1
__device__ float g_asrc[NN * HH];
__device__ float g_adst[NN * HH];
__device__ int   g_cnt[NN];                 // per-dst degree (zeroed by agg for next call)
__device__ int   g_off[NN + 1];             // CSR offsets
__device__ int   g_cur[NN];                 // scatter cursors
__device__ int   g_csr_src[EE];             // src node per edge, bucketed by dst

__device__ __forceinline__ float lrelu(float x, float s) {
    return x >= 0.f ? x : s * x;
}

// ---------------------------------------------------------------------------
// Fused histogram + weight-fusion kernel.
// Blocks [0, HBLK): histogram of dst degrees.
// Blocks [HBLK, HBLK+64): Wf = Wg @ W1 (2 rows per block), bf = Wg @ b1.
// ---------------------------------------------------------------------------
#define HBLK ((EE + 255) / 256)
__global__ void __launch_bounds__(256) hist_wf_kernel(
    const int* __restrict__ ei, const float* __restrict__ Wg,
    const float* __restrict__ W1, const float* __restrict__ b1)
{
    if (blockIdx.x < HBLK) {
        int e = blockIdx.x * 256 + threadIdx.x;
        if (e < EE) atomicAdd(&g_cnt[ei[EE + e]], 1);
    } else {
        int i = (blockIdx.x - HBLK) * 2 + (threadIdx.x >> 7);  // weight row
        int k = threadIdx.x & 127;                              // column
        float acc = 0.f, accb = 0.f;
#pragma unroll 8
        for (int j = 0; j < DD; j++) {
            float w = Wg[i * DD + j];
            acc = fmaf(w, W1[j * DD + k], acc);
            accb = fmaf(w, b1[j], accb);
        }
        g_Wf[i * DD + k] = acc;
        if (k == 0) g_bf[i] = accb;
    }
}

// ---------------------------------------------------------------------------
// GEMM: out[M,128] = leaky(A + prebias, 0.01) @ W^T + bias   (fp32 FFMA)
// If ATTN: also computes g_asrc/g_adst from the output tile in the epilogue.
// ---------------------------------------------------------------------------
template <bool ATTN>
__global__ void __launch_bounds__(256, 1) gemm_kernel(
    const float* __restrict__ A, const float* __restrict__ W,
    const float* __restrict__ prebias, const float* __restrict__ bias,
    const float* __restrict__ attS, const float* __restrict__ attD,
    float* __restrict__ out, int M)
{
    extern __shared__ float4 smem4[];
    float4* As4 = smem4;             // 128 rows x 32 cells
    float4* Bs4 = smem4 + 128 * 32;  // 128 rows x 32 cells

    const int tid = threadIdx.x;
    const int rowBase = blockIdx.x * 128;

#pragma unroll
    for (int i = 0; i < 16; i++) {
        int idx = tid + i * 256;
        int r = idx >> 5;
        int c = idx & 31;
        int row = rowBase + r;
        float4 v = make_float4(0.f, 0.f, 0.f, 0.f);
        if (row < M) v = *(const float4*)(A + (size_t)row * DD + c * 4);
        if (prebias != nullptr) {
            float4 pb = *(const float4*)(prebias + c * 4);
            v.x += pb.x; v.y += pb.y; v.z += pb.z; v.w += pb.w;
        }
        v.x = lrelu(v.x, 0.01f); v.y = lrelu(v.y, 0.01f);
        v.z = lrelu(v.z, 0.01f); v.w = lrelu(v.w, 0.01f);
        As4[r * 32 + (c ^ (r & 31))] = v;
    }
#pragma unroll
    for (int i = 0; i < 16; i++) {
        int idx = tid + i * 256;
        int r = idx >> 5;
        int c = idx & 31;
        float4 v = *(const float4*)(W + (size_t)r * DD + c * 4);
        Bs4[r * 32 + (c ^ (r & 31))] = v;
    }
    __syncthreads();

    const int tx = tid & 15, ty = tid >> 4;
    const int tm = ty * 8, tn = tx * 8;

    float acc[8][8];
#pragma unroll
    for (int i = 0; i < 8; i++)
#pragma unroll
        for (int j = 0; j < 8; j++) acc[i][j] = 0.f;

#pragma unroll 1
    for (int k4 = 0; k4 < 32; k4++) {
        float4 a4[8], b4[8];
#pragma unroll
        for (int i = 0; i < 8; i++)
            a4[i] = As4[(tm + i) * 32 + (k4 ^ ((tm + i) & 31))];
#pragma unroll
        for (int j = 0; j < 8; j++)
            b4[j] = Bs4[(tn + j) * 32 + (k4 ^ ((tn + j) & 31))];
#pragma unroll
        for (int i = 0; i < 8; i++)
#pragma unroll
            for (int j = 0; j < 8; j++) {
                acc[i][j] = fmaf(a4[i].x, b4[j].x, acc[i][j]);
                acc[i][j] = fmaf(a4[i].y, b4[j].y, acc[i][j]);
                acc[i][j] = fmaf(a4[i].z, b4[j].z, acc[i][j]);
                acc[i][j] = fmaf(a4[i].w, b4[j].w, acc[i][j]);
            }
    }

    float bj[8];
#pragma unroll
    for (int j = 0; j < 8; j++) bj[j] = (bias != nullptr) ? bias[tn + j] : 0.f;
#pragma unroll
    for (int i = 0; i < 8; i++)
#pragma unroll
        for (int j = 0; j < 8; j++) acc[i][j] += bj[j];

#pragma unroll
    for (int i = 0; i < 8; i++) {
        int row = rowBase + tm + i;
        if (row < M) {
            *(float4*)(out + (size_t)row * DD + tn) =
                make_float4(acc[i][0], acc[i][1], acc[i][2], acc[i][3]);
            *(float4*)(out + (size_t)row * DD + tn + 4) =
                make_float4(acc[i][4], acc[i][5], acc[i][6], acc[i][7]);
        }
    }

    if (ATTN) {
        float asj[8], adj[8];
#pragma unroll
        for (int j = 0; j < 8; j++) { asj[j] = attS[tn + j]; adj[j] = attD[tn + j]; }
        __syncthreads();  // mainloop done with smem; reuse it
        float* sp = (float*)smem4;          // [128 rows][16 tx]
        float* sd = sp + 128 * 16;
#pragma unroll
        for (int i = 0; i < 8; i++) {
            float ps = 0.f, pd = 0.f;
#pragma unroll
            for (int j = 0; j < 8; j++) {
                ps = fmaf(acc[i][j], asj[j], ps);
                pd = fmaf(acc[i][j], adj[j], pd);
            }
            sp[(tm + i) * 16 + tx] = ps;
            sd[(tm + i) * 16 + tx] = pd;
        }
        __syncthreads();
        if (tid < 128) {
            int row = rowBase + tid;
            if (row < M) {
#pragma unroll
                for (int h = 0; h < 4; h++) {
                    float s = sp[tid * 16 + h * 4 + 0] + sp[tid * 16 + h * 4 + 1]
                            + sp[tid * 16 + h * 4 + 2] + sp[tid * 16 + h * 4 + 3];
                    float d = sd[tid * 16 + h * 4 + 0] + sd[tid * 16 + h * 4 + 1]
                            + sd[tid * 16 + h * 4 + 2] + sd[tid * 16 + h * 4 + 3];
                    g_asrc[row * HH + h] = s;
                    g_adst[row * HH + h] = d;
                }
            }
        }
    }
}

// -------------------------- CSR construction ------------------------------
__global__ void __launch_bounds__(1024) scan_kernel() {
    __shared__ int ssum[1024];
    const int t = threadIdx.x;
    const int CH = (NN + 1023) / 1024;  // 98
    const int base = t * CH;

    int s = 0;
#pragma unroll 4
    for (int i = 0; i < CH; i++) {
        int idx = base + i;
        if (idx < NN) s += g_cnt[idx];
    }
    ssum[t] = s;
    __syncthreads();
    for (int off = 1; off < 1024; off <<= 1) {
        int v = ssum[t];
        int add = (t >= off) ? ssum[t - off] : 0;
        __syncthreads();
        ssum[t] = v + add;
        __syncthreads();
    }
    int run = ssum[t] - s;
    for (int i = 0; i < CH; i++) {
        int idx = base + i;
        if (idx < NN) {
            g_off[idx] = run;
            g_cur[idx] = run;
            run += g_cnt[idx];
        }
    }
    if (t == 1023) g_off[NN] = EE;
}

__global__ void __launch_bounds__(256) scatter_kernel(const int* __restrict__ ei) {
    int e = blockIdx.x * blockDim.x + threadIdx.x;
    if (e >= EE) return;
    int src = ei[e];
    int dst = ei[EE + e];
    int pos = atomicAdd(&g_cur[dst], 1);
    g_csr_src[pos] = src;
}

// ---------------------------------------------------------------------------
// Fused softmax + aggregation: warp per dst. Edge-parallel prefetch + shuffle
// distribution; branch-free fast path for full 8-edge chunks.
// Also zeroes g_cnt[d] for the next call (replaces memset).
// ---------------------------------------------------------------------------
__global__ void __launch_bounds__(256) agg_kernel() {
    int warp = (blockIdx.x * blockDim.x + threadIdx.x) >> 5;
    int lane = threadIdx.x & 31;
    if (warp >= NN) return;
    const int d = warp;
    const int head = lane >> 3;     // consumer head (channel group)
    const int ph = lane & 3;        // producer head
    const int pe = lane >> 2;       // producer edge slot 0..7
    const int beg = g_off[d], end = g_off[d + 1];
    const float adst_ph = g_adst[d * HH + ph];

    if (lane == 0) g_cnt[d] = 0;    // reset histogram for next call

    float4 acc = make_float4(0.f, 0.f, 0.f, 0.f);
    float den = 0.f;

    int base = beg;
    for (; base + 8 <= end; base += 8) {
        int srcl = g_csr_src[base + pe];
        float s = g_asrc[srcl * HH + ph] + adst_ph;
        float exv = expf(lrelu(s, 0.2f));
#pragma unroll
        for (int j = 0; j < 8; j++) {
            float ex = __shfl_sync(0xffffffffu, exv, j * 4 + head);
            int sj = __shfl_sync(0xffffffffu, srcl, j * 4 + head);
            float4 hv = *(const float4*)(g_h + (size_t)sj * DD + lane * 4);
            acc.x = fmaf(ex, hv.x, acc.x);
            acc.y = fmaf(ex, hv.y, acc.y);
            acc.z = fmaf(ex, hv.z, acc.z);
            acc.w = fmaf(ex, hv.w, acc.w);
            den += ex;
        }
    }
    if (base < end) {
        int eidx = base + pe;
        int srcl = 0;
        float exv = 0.f;
        if (eidx < end) {
            srcl = g_csr_src[eidx];
            float s = g_asrc[srcl * HH + ph] + adst_ph;
            exv = expf(lrelu(s, 0.2f));
        }
        int nrem = end - base;
#pragma unroll
        for (int j = 0; j < 8; j++) {
            if (j >= nrem) break;
            float ex = __shfl_sync(0xffffffffu, exv, j * 4 + head);
            int sj = __shfl_sync(0xffffffffu, srcl, j * 4 + head);
            float4 hv = *(const float4*)(g_h + (size_t)sj * DD + lane * 4);
            acc.x = fmaf(ex, hv.x, acc.x);
            acc.y = fmaf(ex, hv.y, acc.y);
            acc.z = fmaf(ex, hv.z, acc.z);
            acc.w = fmaf(ex, hv.w, acc.w);
            den += ex;
        }
    }
    float inv = 1.f / (den + 1e-16f);
    *(float4*)(g_agg + (size_t)d * DD + lane * 4) =
        make_float4(acc.x * inv, acc.y * inv, acc.z * inv, acc.w * inv);
}

// ---------------------------------------------------------------------------
extern "C" void kernel_launch(void* const* d_in, const int* in_sizes, int n_in,
                              void* d_out, int out_size) {
    const float* x       = (const float*)d_in[0];
    const int*   ei      = (const int*)d_in[1];
    // d_in[2] = edge_type (unused by forward)
    const float* W1      = (const float*)d_in[3];
    const float* b1      = (const float*)d_in[4];
    const float* Wg      = (const float*)d_in[5];
    const float* att_src = (const float*)d_in[6];
    const float* att_dst = (const float*)d_in[7];
    const float* bias_g  = (const float*)d_in[8];
    const float* W2      = (const float*)d_in[9];
    const float* b2      = (const float*)d_in[10];
    float* out = (float*)d_out;

    float *ph, *pagg, *pWf, *pbf;
    cudaGetSymbolAddress((void**)&ph, g_h);
    cudaGetSymbolAddress((void**)&pagg, g_agg);
    cudaGetSymbolAddress((void**)&pWf, g_Wf);
    cudaGetSymbolAddress((void**)&pbf, g_bf);

    const int SMEM = 2 * 128 * 128 * 4;  // 128 KB dynamic
    cudaFuncSetAttribute(gemm_kernel<true>,
                         cudaFuncAttributeMaxDynamicSharedMemorySize, SMEM);
    cudaFuncSetAttribute(gemm_kernel<false>,
                         cudaFuncAttributeMaxDynamicSharedMemorySize, SMEM);

    const int gblocks = (NN + 127) / 128;  // 782

    // 1: dst histogram + Wf = Wg@W1 / bf = Wg@b1 (fused grid)
    hist_wf_kernel<<<HBLK + 64, 256>>>(ei, Wg, W1, b1);
    // 2: CSR offsets
    scan_kernel<<<1, 1024>>>();
    // 3: CSR scatter
    scatter_kernel<<<(EE + 255) / 256, 256>>>(ei);
    // 4: h = leaky(x)@Wf^T + bf, with fused attention-score epilogue
    gemm_kernel<true><<<gblocks, 256, SMEM>>>(x, pWf, nullptr, pbf,
                                              att_src, att_dst, ph, NN);
    // 5: fused softmax + aggregation (profiled launch)
    agg_kernel<<<(NN * 32 + 255) / 256, 256>>>();
    // 6: out = leaky(agg + bias_g)@W2^T + b2
    gemm_kernel<false><<<gblocks, 256, SMEM>>>(pagg, W2, bias_g, b2,
                                               nullptr, nullptr, out, NN);
}

// round 6
// speedup vs baseline: 2.1519x; 1.5405x over previous
#include <cuda_runtime.h>
#include <math.h>

#define NN 100000
#define EE 1600000
#define DD 128
#define HH 4

// ---------------- device scratch (static globals: allocation-free rule) ----
__device__ float g_h[(size_t)NN * DD];      // after fused linear1+GAT lin
__device__ float g_agg[(size_t)NN * DD];    // aggregated messages
__device__ float g_Wf[DD * DD];             // Wg @ W1
__device__ float g_bf[DD];                  // Wg @ b1
__device__ float g_asrc[NN * HH];
__device__ float g_adst[NN * HH];
__device__ int   g_cnt[NN];                 // per-dst degree (zeroed by agg for next call)
__device__ int   g_off[NN + 1];             // CSR offsets
__device__ int   g_cur[NN];                 // scatter cursors
__device__ int   g_csr_src[EE];             // src node per edge, bucketed by dst

__device__ __forceinline__ float lrelu(float x, float s) {
    return x >= 0.f ? x : s * x;
}

// ---------------------------------------------------------------------------
// Fused histogram + weight-fusion kernel.
// ---------------------------------------------------------------------------
#define HBLK ((EE + 255) / 256)
__global__ void __launch_bounds__(256) hist_wf_kernel(
    const int* __restrict__ ei, const float* __restrict__ Wg,
    const float* __restrict__ W1, const float* __restrict__ b1)
{
    if (blockIdx.x < HBLK) {
        int e = blockIdx.x * 256 + threadIdx.x;
        if (e < EE) atomicAdd(&g_cnt[ei[EE + e]], 1);
    } else {
        int i = (blockIdx.x - HBLK) * 2 + (threadIdx.x >> 7);  // weight row
        int k = threadIdx.x & 127;                              // column
        float acc = 0.f, accb = 0.f;
#pragma unroll 8
        for (int j = 0; j < DD; j++) {
            float w = Wg[i * DD + j];
            acc = fmaf(w, W1[j * DD + k], acc);
            accb = fmaf(w, b1[j], accb);
        }
        g_Wf[i * DD + k] = acc;
        if (k == 0) g_bf[i] = accb;
    }
}

// ---------------------------------------------------------------------------
// GEMM: out[M,128] = leaky(A + prebias, 0.01) @ W^T + bias   (fp32 FFMA)
// Smem swizzle: cell = c ^ (r>>3).  B-operand compute reads then have
// bank-quad = (k4 ^ tx) & 7 -> 8 distinct quads per phase (conflict-free);
// A reads are phase-broadcast; staging writes are lane-distinct. (The old
// c ^ (r&31) swizzle gave an 8-way conflict on every B read.)
// If ATTN: also computes g_asrc/g_adst from the output tile in the epilogue.
// ---------------------------------------------------------------------------
template <bool ATTN>
__global__ void __launch_bounds__(256, 1) gemm_kernel(
    const float* __restrict__ A, const float* __restrict__ W,
    const float* __restrict__ prebias, const float* __restrict__ bias,
    const float* __restrict__ attS, const float* __restrict__ attD,
    float* __restrict__ out, int M)
{
    extern __shared__ float4 smem4[];
    float4* As4 = smem4;             // 128 rows x 32 cells
    float4* Bs4 = smem4 + 128 * 32;  // 128 rows x 32 cells

    const int tid = threadIdx.x;
    const int rowBase = blockIdx.x * 128;

#pragma unroll
    for (int i = 0; i < 16; i++) {
        int idx = tid + i * 256;
        int r = idx >> 5;
        int c = idx & 31;
        int row = rowBase + r;
        float4 v = make_float4(0.f, 0.f, 0.f, 0.f);
        if (row < M) v = *(const float4*)(A + (size_t)row * DD + c * 4);
        if (prebias != nullptr) {
            float4 pb = *(const float4*)(prebias + c * 4);
            v.x += pb.x; v.y += pb.y; v.z += pb.z; v.w += pb.w;
        }
        v.x = lrelu(v.x, 0.01f); v.y = lrelu(v.y, 0.01f);
        v.z = lrelu(v.z, 0.01f); v.w = lrelu(v.w, 0.01f);
        As4[r * 32 + (c ^ (r >> 3))] = v;
    }
#pragma unroll
    for (int i = 0; i < 16; i++) {
        int idx = tid + i * 256;
        int r = idx >> 5;
        int c = idx & 31;
        float4 v = *(const float4*)(W + (size_t)r * DD + c * 4);
        Bs4[r * 32 + (c ^ (r >> 3))] = v;
    }
    __syncthreads();

    const int tx = tid & 15, ty = tid >> 4;
    const int tm = ty * 8, tn = tx * 8;

    float acc[8][8];
#pragma unroll
    for (int i = 0; i < 8; i++)
#pragma unroll
        for (int j = 0; j < 8; j++) acc[i][j] = 0.f;

#pragma unroll 1
    for (int k4 = 0; k4 < 32; k4++) {
        float4 a4[8], b4[8];
#pragma unroll
        for (int i = 0; i < 8; i++)
            a4[i] = As4[(tm + i) * 32 + (k4 ^ ((tm + i) >> 3))];
#pragma unroll
        for (int j = 0; j < 8; j++)
            b4[j] = Bs4[(tn + j) * 32 + (k4 ^ ((tn + j) >> 3))];
#pragma unroll
        for (int i = 0; i < 8; i++)
#pragma unroll
            for (int j = 0; j < 8; j++) {
                acc[i][j] = fmaf(a4[i].x, b4[j].x, acc[i][j]);
                acc[i][j] = fmaf(a4[i].y, b4[j].y, acc[i][j]);
                acc[i][j] = fmaf(a4[i].z, b4[j].z, acc[i][j]);
                acc[i][j] = fmaf(a4[i].w, b4[j].w, acc[i][j]);
            }
    }

    float bj[8];
#pragma unroll
    for (int j = 0; j < 8; j++) bj[j] = (bias != nullptr) ? bias[tn + j] : 0.f;
#pragma unroll
    for (int i = 0; i < 8; i++)
#pragma unroll
        for (int j = 0; j < 8; j++) acc[i][j] += bj[j];

#pragma unroll
    for (int i = 0; i < 8; i++) {
        int row = rowBase + tm + i;
        if (row < M) {
            *(float4*)(out + (size_t)row * DD + tn) =
                make_float4(acc[i][0], acc[i][1], acc[i][2], acc[i][3]);
            *(float4*)(out + (size_t)row * DD + tn + 4) =
                make_float4(acc[i][4], acc[i][5], acc[i][6], acc[i][7]);
        }
    }

    if (ATTN) {
        float asj[8], adj[8];
#pragma unroll
        for (int j = 0; j < 8; j++) { asj[j] = attS[tn + j]; adj[j] = attD[tn + j]; }
        __syncthreads();  // mainloop done with smem; reuse it
        float* sp = (float*)smem4;          // [128 rows][16 tx]
        float* sd = sp + 128 * 16;
#pragma unroll
        for (int i = 0; i < 8; i++) {
            float ps = 0.f, pd = 0.f;
#pragma unroll
            for (int j = 0; j < 8; j++) {
                ps = fmaf(acc[i][j], asj[j], ps);
                pd = fmaf(acc[i][j], adj[j], pd);
            }
            sp[(tm + i) * 16 + tx] = ps;
            sd[(tm + i) * 16 + tx] = pd;
        }
        __syncthreads();
        if (tid < 128) {
            int row = rowBase + tid;
            if (row < M) {
#pragma unroll
                for (int h = 0; h < 4; h++) {
                    float s = sp[tid * 16 + h * 4 + 0] + sp[tid * 16 + h * 4 + 1]
                            + sp[tid * 16 + h * 4 + 2] + sp[tid * 16 + h * 4 + 3];
                    float d = sd[tid * 16 + h * 4 + 0] + sd[tid * 16 + h * 4 + 1]
                            + sd[tid * 16 + h * 4 + 2] + sd[tid * 16 + h * 4 + 3];
                    g_asrc[row * HH + h] = s;
                    g_adst[row * HH + h] = d;
                }
            }
        }
    }
}

// -------------------------- CSR construction ------------------------------
__global__ void __launch_bounds__(1024) scan_kernel() {
    __shared__ int ssum[1024];
    const int t = threadIdx.x;
    const int CH = (NN + 1023) / 1024;  // 98
    const int base = t * CH;

    int s = 0;
#pragma unroll 4
    for (int i = 0; i < CH; i++) {
        int idx = base + i;
        if (idx < NN) s += g_cnt[idx];
    }
    ssum[t] = s;
    __syncthreads();
    for (int off = 1; off < 1024; off <<= 1) {
        int v = ssum[t];
        int add = (t >= off) ? ssum[t - off] : 0;
        __syncthreads();
        ssum[t] = v + add;
        __syncthreads();
    }
    int run = ssum[t] - s;
    for (int i = 0; i < CH; i++) {
        int idx = base + i;
        if (idx < NN) {
            g_off[idx] = run;
            g_cur[idx] = run;
            run += g_cnt[idx];
        }
    }
    if (t == 1023) g_off[NN] = EE;
}

__global__ void __launch_bounds__(256) scatter_kernel(const int* __restrict__ ei) {
    int e = blockIdx.x * blockDim.x + threadIdx.x;
    if (e >= EE) return;
    int src = ei[e];
    int dst = ei[EE + e];
    int pos = atomicAdd(&g_cur[dst], 1);
    g_csr_src[pos] = src;
}

// ---------------------------------------------------------------------------
// Fused softmax + aggregation: warp per dst. Edge-parallel prefetch + shuffle
// distribution; branch-free fast path for full 8-edge chunks.
// Also zeroes g_cnt[d] for the next call (replaces memset).
// ---------------------------------------------------------------------------
__global__ void __launch_bounds__(256) agg_kernel() {
    int warp = (blockIdx.x * blockDim.x + threadIdx.x) >> 5;
    int lane = threadIdx.x & 31;
    if (warp >= NN) return;
    const int d = warp;
    const int head = lane >> 3;     // consumer head (channel group)
    const int ph = lane & 3;        // producer head
    const int pe = lane >> 2;       // producer edge slot 0..7
    const int beg = g_off[d], end = g_off[d + 1];
    const float adst_ph = g_adst[d * HH + ph];

    if (lane == 0) g_cnt[d] = 0;    // reset histogram for next call

    float4 acc = make_float4(0.f, 0.f, 0.f, 0.f);
    float den = 0.f;

    int base = beg;
    for (; base + 8 <= end; base += 8) {
        int srcl = g_csr_src[base + pe];
        float s = g_asrc[srcl * HH + ph] + adst_ph;
        float exv = __expf(lrelu(s, 0.2f));
#pragma unroll
        for (int j = 0; j < 8; j++) {
            float ex = __shfl_sync(0xffffffffu, exv, j * 4 + head);
            int sj = __shfl_sync(0xffffffffu, srcl, j * 4 + head);
            float4 hv = *(const float4*)(g_h + (size_t)sj * DD + lane * 4);
            acc.x = fmaf(ex, hv.x, acc.x);
            acc.y = fmaf(ex, hv.y, acc.y);
            acc.z = fmaf(ex, hv.z, acc.z);
            acc.w = fmaf(ex, hv.w, acc.w);
            den += ex;
        }
    }
    if (base < end) {
        int eidx = base + pe;
        int srcl = 0;
        float exv = 0.f;
        if (eidx < end) {
            srcl = g_csr_src[eidx];
            float s = g_asrc[srcl * HH + ph] + adst_ph;
            exv = __expf(lrelu(s, 0.2f));
        }
        int nrem = end - base;
#pragma unroll
        for (int j = 0; j < 8; j++) {
            if (j >= nrem) break;
            float ex = __shfl_sync(0xffffffffu, exv, j * 4 + head);
            int sj = __shfl_sync(0xffffffffu, srcl, j * 4 + head);
            float4 hv = *(const float4*)(g_h + (size_t)sj * DD + lane * 4);
            acc.x = fmaf(ex, hv.x, acc.x);
            acc.y = fmaf(ex, hv.y, acc.y);
            acc.z = fmaf(ex, hv.z, acc.z);
            acc.w = fmaf(ex, hv.w, acc.w);
            den += ex;
        }
    }
    float inv = 1.f / (den + 1e-16f);
    *(float4*)(g_agg + (size_t)d * DD + lane * 4) =
        make_float4(acc.x * inv, acc.y * inv, acc.z * inv, acc.w * inv);
}

// ---------------------------------------------------------------------------
extern "C" void kernel_launch(void* const* d_in, const int* in_sizes, int n_in,
                              void* d_out, int out_size) {
    const float* x       = (const float*)d_in[0];
    const int*   ei      = (const int*)d_in[1];
    // d_in[2] = edge_type (unused by forward)
    const float* W1      = (const float*)d_in[3];
    const float* b1      = (const float*)d_in[4];
    const float* Wg      = (const float*)d_in[5];
    const float* att_src = (const float*)d_in[6];
    const float* att_dst = (const float*)d_in[7];
    const float* bias_g  = (const float*)d_in[8];
    const float* W2      = (const float*)d_in[9];
    const float* b2      = (const float*)d_in[10];
    float* out = (float*)d_out;

    float *ph, *pagg, *pWf, *pbf;
    cudaGetSymbolAddress((void**)&ph, g_h);
    cudaGetSymbolAddress((void**)&pagg, g_agg);
    cudaGetSymbolAddress((void**)&pWf, g_Wf);
    cudaGetSymbolAddress((void**)&pbf, g_bf);

    const int SMEM = 2 * 128 * 128 * 4;  // 128 KB dynamic
    cudaFuncSetAttribute(gemm_kernel<true>,
                         cudaFuncAttributeMaxDynamicSharedMemorySize, SMEM);
    cudaFuncSetAttribute(gemm_kernel<false>,
                         cudaFuncAttributeMaxDynamicSharedMemorySize, SMEM);

    const int gblocks = (NN + 127) / 128;  // 782

    // 1: dst histogram + Wf = Wg@W1 / bf = Wg@b1 (fused grid)
    hist_wf_kernel<<<HBLK + 64, 256>>>(ei, Wg, W1, b1);
    // 2: CSR offsets
    scan_kernel<<<1, 1024>>>();
    // 3: CSR scatter
    scatter_kernel<<<(EE + 255) / 256, 256>>>(ei);
    // 4: h = leaky(x)@Wf^T + bf, with fused attention-score epilogue
    gemm_kernel<true><<<gblocks, 256, SMEM>>>(x, pWf, nullptr, pbf,
                                              att_src, att_dst, ph, NN);
    // 5: fused softmax + aggregation
    agg_kernel<<<(NN * 32 + 255) / 256, 256>>>();
    // 6: out = leaky(agg + bias_g)@W2^T + b2
    gemm_kernel<false><<<gblocks, 256, SMEM>>>(pagg, W2, bias_g, b2,
                                               nullptr, nullptr, out, NN);
}

// round 7
// speedup vs baseline: 2.2183x; 1.0308x over previous
#include <cuda_runtime.h>
#include <cuda_fp16.h>
#include <math.h>

#define NN 100000
#define EE 1600000
#define DD 128
#define HH 4

// ---------------- device scratch (static globals: allocation-free rule) ----
__device__ float  g_h[(size_t)NN * DD];     // after fused linear1+GAT lin (fp32)
__device__ __half g_h16[(size_t)NN * DD];   // fp16 mirror for agg gather
__device__ float  g_agg[(size_t)NN * DD];   // aggregated messages
__device__ float  g_Wf[DD * DD];            // Wg @ W1
__device__ float  g_bf[DD];                 // Wg @ b1
__device__ float  g_asrc[NN * HH];
__device__ float  g_adst[NN * HH];
__device__ int    g_cnt[NN];                // per-dst degree (zeroed by agg for next call)
__device__ int    g_off[NN + 1];            // CSR offsets
__device__ int    g_cur[NN];                // scatter cursors
__device__ int    g_csr_src[EE];            // src node per edge, bucketed by dst

__device__ __forceinline__ float lrelu(float x, float s) {
    return x >= 0.f ? x : s * x;
}

// packed dual-FMA: d.lo += a.lo*b.lo; d.hi += a.hi*b.hi   (B300 FFMA2 path,
// only reachable via explicit PTX fma.rn.f32x2; sm_100+ non-suffixed feature)
__device__ __forceinline__ void ffma2(unsigned long long& d, double a, double b) {
    asm("fma.rn.f32x2 %0, %1, %2, %0;"
        : "+l"(d)
        : "l"(__double_as_longlong(a)), "l"(__double_as_longlong(b)));
}
__device__ __forceinline__ float unpack_sum(unsigned long long v) {
    return __int_as_float((unsigned)(v & 0xffffffffu)) +
           __int_as_float((unsigned)(v >> 32));
}

// ---------------------------------------------------------------------------
// Fused histogram + weight-fusion kernel.
// ---------------------------------------------------------------------------
#define HBLK ((EE + 255) / 256)
__global__ void __launch_bounds__(256) hist_wf_kernel(
    const int* __restrict__ ei, const float* __restrict__ Wg,
    const float* __restrict__ W1, const float* __restrict__ b1)
{
    if (blockIdx.x < HBLK) {
        int e = blockIdx.x * 256 + threadIdx.x;
        if (e < EE) atomicAdd(&g_cnt[ei[EE + e]], 1);
    } else {
        int i = (blockIdx.x - HBLK) * 2 + (threadIdx.x >> 7);  // weight row
        int k = threadIdx.x & 127;                              // column
        float acc = 0.f, accb = 0.f;
#pragma unroll 8
        for (int j = 0; j < DD; j++) {
            float w = Wg[i * DD + j];
            acc = fmaf(w, W1[j * DD + k], acc);
            accb = fmaf(w, b1[j], accb);
        }
        g_Wf[i * DD + k] = acc;
        if (k == 0) g_bf[i] = accb;
    }
}

// ---------------------------------------------------------------------------
// GEMM: out[M,128] = leaky(A + prebias, 0.01) @ W^T + bias
// Inner product via packed fma.rn.f32x2 over k-pairs: accumulator holds
// (even-k, odd-k) partials, summed once at the end. Operands are natural
// 8-byte views of the k-major smem tiles (swizzle cell = c ^ (r>>3),
// conflict-free for both staging and compute reads).
// If ATTN: also writes fp16 mirror g_h16 and attention scores.
// ---------------------------------------------------------------------------
template <bool ATTN>
__global__ void __launch_bounds__(256, 1) gemm_kernel(
    const float* __restrict__ A, const float* __restrict__ W,
    const float* __restrict__ prebias, const float* __restrict__ bias,
    const float* __restrict__ attS, const float* __restrict__ attD,
    float* __restrict__ out, int M)
{
    extern __shared__ float4 smem4[];
    float4* As4 = smem4;             // 128 rows x 32 cells
    float4* Bs4 = smem4 + 128 * 32;  // 128 rows x 32 cells

    const int tid = threadIdx.x;
    const int rowBase = blockIdx.x * 128;

#pragma unroll
    for (int i = 0; i < 16; i++) {
        int idx = tid + i * 256;
        int r = idx >> 5;
        int c = idx & 31;
        int row = rowBase + r;
        float4 v = make_float4(0.f, 0.f, 0.f, 0.f);
        if (row < M) v = *(const float4*)(A + (size_t)row * DD + c * 4);
        if (prebias != nullptr) {
            float4 pb = *(const float4*)(prebias + c * 4);
            v.x += pb.x; v.y += pb.y; v.z += pb.z; v.w += pb.w;
        }
        v.x = lrelu(v.x, 0.01f); v.y = lrelu(v.y, 0.01f);
        v.z = lrelu(v.z, 0.01f); v.w = lrelu(v.w, 0.01f);
        As4[r * 32 + (c ^ (r >> 3))] = v;
    }
#pragma unroll
    for (int i = 0; i < 16; i++) {
        int idx = tid + i * 256;
        int r = idx >> 5;
        int c = idx & 31;
        float4 v = *(const float4*)(W + (size_t)r * DD + c * 4);
        Bs4[r * 32 + (c ^ (r >> 3))] = v;
    }
    __syncthreads();

    const int tx = tid & 15, ty = tid >> 4;
    const int tm = ty * 8, tn = tx * 8;

    unsigned long long acc2[8][8];
#pragma unroll
    for (int i = 0; i < 8; i++)
#pragma unroll
        for (int j = 0; j < 8; j++) acc2[i][j] = 0ull;

#pragma unroll 1
    for (int k4 = 0; k4 < 32; k4++) {
        double2 a2[8], b2[8];
#pragma unroll
        for (int i = 0; i < 8; i++)
            a2[i] = *(const double2*)&As4[(tm + i) * 32 + (k4 ^ ((tm + i) >> 3))];
#pragma unroll
        for (int j = 0; j < 8; j++)
            b2[j] = *(const double2*)&Bs4[(tn + j) * 32 + (k4 ^ ((tn + j) >> 3))];
#pragma unroll
        for (int i = 0; i < 8; i++)
#pragma unroll
            for (int j = 0; j < 8; j++) {
                ffma2(acc2[i][j], a2[i].x, b2[j].x);
                ffma2(acc2[i][j], a2[i].y, b2[j].y);
            }
    }

    float bj[8];
#pragma unroll
    for (int j = 0; j < 8; j++) bj[j] = (bias != nullptr) ? bias[tn + j] : 0.f;

    float acc[8][8];
#pragma unroll
    for (int i = 0; i < 8; i++)
#pragma unroll
        for (int j = 0; j < 8; j++) acc[i][j] = unpack_sum(acc2[i][j]) + bj[j];

#pragma unroll
    for (int i = 0; i < 8; i++) {
        int row = rowBase + tm + i;
        if (row < M) {
            *(float4*)(out + (size_t)row * DD + tn) =
                make_float4(acc[i][0], acc[i][1], acc[i][2], acc[i][3]);
            *(float4*)(out + (size_t)row * DD + tn + 4) =
                make_float4(acc[i][4], acc[i][5], acc[i][6], acc[i][7]);
            if (ATTN) {
                __half2 hp[4];
#pragma unroll
                for (int q = 0; q < 4; q++)
                    hp[q] = __floats2half2_rn(acc[i][2 * q], acc[i][2 * q + 1]);
                *(uint2*)(g_h16 + (size_t)row * DD + tn) =
                    make_uint2(*(unsigned*)&hp[0], *(unsigned*)&hp[1]);
                *(uint2*)(g_h16 + (size_t)row * DD + tn + 4) =
                    make_uint2(*(unsigned*)&hp[2], *(unsigned*)&hp[3]);
            }
        }
    }

    if (ATTN) {
        float asj[8], adj[8];
#pragma unroll
        for (int j = 0; j < 8; j++) { asj[j] = attS[tn + j]; adj[j] = attD[tn + j]; }
        __syncthreads();  // mainloop done with smem; reuse it
        float* sp = (float*)smem4;          // [128 rows][16 tx]
        float* sd = sp + 128 * 16;
#pragma unroll
        for (int i = 0; i < 8; i++) {
            float ps = 0.f, pd = 0.f;
#pragma unroll
            for (int j = 0; j < 8; j++) {
                ps = fmaf(acc[i][j], asj[j], ps);
                pd = fmaf(acc[i][j], adj[j], pd);
            }
            sp[(tm + i) * 16 + tx] = ps;
            sd[(tm + i) * 16 + tx] = pd;
        }
        __syncthreads();
        if (tid < 128) {
            int row = rowBase + tid;
            if (row < M) {
#pragma unroll
                for (int h = 0; h < 4; h++) {
                    float s = sp[tid * 16 + h * 4 + 0] + sp[tid * 16 + h * 4 + 1]
                            + sp[tid * 16 + h * 4 + 2] + sp[tid * 16 + h * 4 + 3];
                    float d = sd[tid * 16 + h * 4 + 0] + sd[tid * 16 + h * 4 + 1]
                            + sd[tid * 16 + h * 4 + 2] + sd[tid * 16 + h * 4 + 3];
                    g_asrc[row * HH + h] = s;
                    g_adst[row * HH + h] = d;
                }
            }
        }
    }
}

// -------------------------- CSR construction ------------------------------
__global__ void __launch_bounds__(1024) scan_kernel() {
    __shared__ int ssum[1024];
    const int t = threadIdx.x;
    const int CH = (NN + 1023) / 1024;  // 98
    const int base = t * CH;

    int s = 0;
#pragma unroll 4
    for (int i = 0; i < CH; i++) {
        int idx = base + i;
        if (idx < NN) s += g_cnt[idx];
    }
    ssum[t] = s;
    __syncthreads();
    for (int off = 1; off < 1024; off <<= 1) {
        int v = ssum[t];
        int add = (t >= off) ? ssum[t - off] : 0;
        __syncthreads();
        ssum[t] = v + add;
        __syncthreads();
    }
    int run = ssum[t] - s;
    for (int i = 0; i < CH; i++) {
        int idx = base + i;
        if (idx < NN) {
            g_off[idx] = run;
            g_cur[idx] = run;
            run += g_cnt[idx];
        }
    }
    if (t == 1023) g_off[NN] = EE;
}

__global__ void __launch_bounds__(256) scatter_kernel(const int* __restrict__ ei) {
    int e = blockIdx.x * blockDim.x + threadIdx.x;
    if (e >= EE) return;
    int src = ei[e];
    int dst = ei[EE + e];
    int pos = atomicAdd(&g_cur[dst], 1);
    g_csr_src[pos] = src;
}

// ---------------------------------------------------------------------------
// Fused softmax + aggregation: warp per dst. Edge-parallel exp prefetch +
// shuffle distribution; messages gathered from the fp16 mirror (half traffic).
// Also zeroes g_cnt[d] for the next call.
// ---------------------------------------------------------------------------
__global__ void __launch_bounds__(256) agg_kernel() {
    int warp = (blockIdx.x * blockDim.x + threadIdx.x) >> 5;
    int lane = threadIdx.x & 31;
    if (warp >= NN) return;
    const int d = warp;
    const int head = lane >> 3;     // consumer head (channel group)
    const int ph = lane & 3;        // producer head
    const int pe = lane >> 2;       // producer edge slot 0..7
    const int beg = g_off[d], end = g_off[d + 1];
    const float adst_ph = g_adst[d * HH + ph];

    if (lane == 0) g_cnt[d] = 0;    // reset histogram for next call

    float4 acc = make_float4(0.f, 0.f, 0.f, 0.f);
    float den = 0.f;

    int base = beg;
    for (; base + 8 <= end; base += 8) {
        int srcl = g_csr_src[base + pe];
        float s = g_asrc[srcl * HH + ph] + adst_ph;
        float exv = __expf(lrelu(s, 0.2f));
#pragma unroll
        for (int j = 0; j < 8; j++) {
            float ex = __shfl_sync(0xffffffffu, exv, j * 4 + head);
            int sj = __shfl_sync(0xffffffffu, srcl, j * 4 + head);
            uint2 u = *(const uint2*)(g_h16 + (size_t)sj * DD + lane * 4);
            float2 f0 = __half22float2(*(__half2*)&u.x);
            float2 f1 = __half22float2(*(__half2*)&u.y);
            acc.x = fmaf(ex, f0.x, acc.x);
            acc.y = fmaf(ex, f0.y, acc.y);
            acc.z = fmaf(ex, f1.x, acc.z);
            acc.w = fmaf(ex, f1.y, acc.w);
            den += ex;
        }
    }
    if (base < end) {
        int eidx = base + pe;
        int srcl = 0;
        float exv = 0.f;
        if (eidx < end) {
            srcl = g_csr_src[eidx];
            float s = g_asrc[srcl * HH + ph] + adst_ph;
            exv = __expf(lrelu(s, 0.2f));
        }
        int nrem = end - base;
#pragma unroll
        for (int j = 0; j < 8; j++) {
            if (j >= nrem) break;
            float ex = __shfl_sync(0xffffffffu, exv, j * 4 + head);
            int sj = __shfl_sync(0xffffffffu, srcl, j * 4 + head);
            uint2 u = *(const uint2*)(g_h16 + (size_t)sj * DD + lane * 4);
            float2 f0 = __half22float2(*(__half2*)&u.x);
            float2 f1 = __half22float2(*(__half2*)&u.y);
            acc.x = fmaf(ex, f0.x, acc.x);
            acc.y = fmaf(ex, f0.y, acc.y);
            acc.z = fmaf(ex, f1.x, acc.z);
            acc.w = fmaf(ex, f1.y, acc.w);
            den += ex;
        }
    }
    float inv = 1.f / (den + 1e-16f);
    *(float4*)(g_agg + (size_t)d * DD + lane * 4) =
        make_float4(acc.x * inv, acc.y * inv, acc.z * inv, acc.w * inv);
}

// ---------------------------------------------------------------------------
extern "C" void kernel_launch(void* const* d_in, const int* in_sizes, int n_in,
                              void* d_out, int out_size) {
    const float* x       = (const float*)d_in[0];
    const int*   ei      = (const int*)d_in[1];
    // d_in[2] = edge_type (unused by forward)
    const float* W1      = (const float*)d_in[3];
    const float* b1      = (const float*)d_in[4];
    const float* Wg      = (const float*)d_in[5];
    const float* att_src = (const float*)d_in[6];
    const float* att_dst = (const float*)d_in[7];
    const float* bias_g  = (const float*)d_in[8];
    const float* W2      = (const float*)d_in[9];
    const float* b2      = (const float*)d_in[10];
    float* out = (float*)d_out;

    float *ph, *pagg, *pWf, *pbf;
    cudaGetSymbolAddress((void**)&ph, g_h);
    cudaGetSymbolAddress((void**)&pagg, g_agg);
    cudaGetSymbolAddress((void**)&pWf, g_Wf);
    cudaGetSymbolAddress((void**)&pbf, g_bf);

    const int SMEM = 2 * 128 * 128 * 4;  // 128 KB dynamic
    cudaFuncSetAttribute(gemm_kernel<true>,
                         cudaFuncAttributeMaxDynamicSharedMemorySize, SMEM);
    cudaFuncSetAttribute(gemm_kernel<false>,
                         cudaFuncAttributeMaxDynamicSharedMemorySize, SMEM);

    const int gblocks = (NN + 127) / 128;  // 782

    // 1: dst histogram + Wf = Wg@W1 / bf = Wg@b1 (fused grid)
    hist_wf_kernel<<<HBLK + 64, 256>>>(ei, Wg, W1, b1);
    // 2: CSR offsets
    scan_kernel<<<1, 1024>>>();
    // 3: CSR scatter
    scatter_kernel<<<(EE + 255) / 256, 256>>>(ei);
    // 4: h = leaky(x)@Wf^T + bf, with fused attention-score + fp16-mirror epilogue
    gemm_kernel<true><<<gblocks, 256, SMEM>>>(x, pWf, nullptr, pbf,
                                              att_src, att_dst, ph, NN);
    // 5: fused softmax + aggregation (fp16 gathers)
    agg_kernel<<<(NN * 32 + 255) / 256, 256>>>();
    // 6: out = leaky(agg + bias_g)@W2^T + b2
    gemm_kernel<false><<<gblocks, 256, SMEM>>>(pagg, W2, bias_g, b2,
                                               nullptr, nullptr, out, NN);
}

// round 8
// speedup vs baseline: 2.6700x; 1.2036x over previous
#include <cuda_runtime.h>
#include <cuda_bf16.h>
#include <cuda_fp16.h>
#include <math.h>
#include <cstdint>

#define NN 100000
#define EE 1600000
#define DD 128
#define HH 4

// ---------------- device scratch (static globals: allocation-free rule) ----
__device__ __half g_h16[(size_t)NN * DD];   // fp16 h for agg gather (only copy)
__device__ float  g_agg[(size_t)NN * DD];   // aggregated messages
__device__ float  g_Wf[DD * DD];            // Wg @ W1
__device__ float  g_bf[DD];                 // Wg @ b1
__device__ float  g_asrc[NN * HH];
__device__ float  g_adst[NN * HH];
__device__ int    g_cnt[NN];                // per-dst degree (zeroed by agg)
__device__ int    g_off[NN + 1];            // CSR offsets
__device__ int    g_cur[NN];                // scatter cursors
__device__ int    g_csr_src[EE];            // src per edge, bucketed by dst

__device__ __forceinline__ float lrelu(float x, float s) {
    return x >= 0.f ? x : s * x;
}
__device__ __forceinline__ uint32_t smem_u32(const void* p) {
    uint32_t a;
    asm("{ .reg .u64 t; cvta.to.shared.u64 t, %1; cvt.u32.u64 %0, t; }"
        : "=r"(a) : "l"(p));
    return a;
}
__device__ __forceinline__ uint32_t pack_bf2(float a, float b) {
    __nv_bfloat162 t = __floats2bfloat162_rn(a, b);
    return *reinterpret_cast<uint32_t*>(&t);
}
__device__ __forceinline__ void ldsm_x4(uint32_t& r0, uint32_t& r1,
                                        uint32_t& r2, uint32_t& r3, uint32_t a) {
    asm volatile("ldmatrix.sync.aligned.m8n8.x4.shared.b16 {%0,%1,%2,%3}, [%4];"
                 : "=r"(r0), "=r"(r1), "=r"(r2), "=r"(r3) : "r"(a));
}
__device__ __forceinline__ void ldsm_x2(uint32_t& r0, uint32_t& r1, uint32_t a) {
    asm volatile("ldmatrix.sync.aligned.m8n8.x2.shared.b16 {%0,%1}, [%2];"
                 : "=r"(r0), "=r"(r1) : "r"(a));
}
__device__ __forceinline__ void mma16816(float* d, const uint32_t* a,
                                         const uint32_t* b) {
    asm volatile("mma.sync.aligned.m16n8k16.row.col.f32.bf16.bf16.f32 "
                 "{%0,%1,%2,%3}, {%4,%5,%6,%7}, {%8,%9}, {%0,%1,%2,%3};"
                 : "+f"(d[0]), "+f"(d[1]), "+f"(d[2]), "+f"(d[3])
                 : "r"(a[0]), "r"(a[1]), "r"(a[2]), "r"(a[3]),
                   "r"(b[0]), "r"(b[1]));
}

// ---------------------------------------------------------------------------
// Fused histogram + weight fusion (Wf = Wg@W1, bf = Wg@b1).
// ---------------------------------------------------------------------------
#define HBLK ((EE + 255) / 256)
__global__ void __launch_bounds__(256) hist_wf_kernel(
    const int* __restrict__ ei, const float* __restrict__ Wg,
    const float* __restrict__ W1, const float* __restrict__ b1)
{
    if (blockIdx.x < HBLK) {
        int e = blockIdx.x * 256 + threadIdx.x;
        if (e < EE) atomicAdd(&g_cnt[ei[EE + e]], 1);
    } else {
        int i = (blockIdx.x - HBLK) * 2 + (threadIdx.x >> 7);
        int k = threadIdx.x & 127;
        float acc = 0.f, accb = 0.f;
#pragma unroll 8
        for (int j = 0; j < DD; j++) {
            float w = Wg[i * DD + j];
            acc = fmaf(w, W1[j * DD + k], acc);
            accb = fmaf(w, b1[j], accb);
        }
        g_Wf[i * DD + k] = acc;
        if (k == 0) g_bf[i] = accb;
    }
}

// ---------------------------------------------------------------------------
// HMMA GEMM: out[M,128] = leaky(A + prebias, 0.01) @ W^T + bias
// fp32 operands split into bf16 hi/lo; D = AhWh + AhWl + AlWh (fp32 accum).
// smem: 4 bf16 tiles [128][128] (Ah, Al, Wh, Wl), row = 256B, 16B granule g
// stored at (g ^ (r&7)) -> conflict-free staging stores AND ldmatrix reads.
// Warp grid 2(m)x4(n); per warp 4x4 m16n8 tiles, K in 8 k16 steps.
// ATTN variant: scatter prologue (CSR fill), writes fp16 h mirror + attention
// scores instead of the fp32 out tile.
// ---------------------------------------------------------------------------
template <bool ATTN>
__global__ void __launch_bounds__(256, 1) gemm_kernel(
    const float* __restrict__ A, const float* __restrict__ W,
    const float* __restrict__ prebias, const float* __restrict__ bias,
    const float* __restrict__ attS, const float* __restrict__ attD,
    float* __restrict__ out, int M, const int* __restrict__ ei)
{
    extern __shared__ char smem[];
    const int tid = threadIdx.x;

    if (ATTN) {  // fused CSR scatter (independent of GEMM work)
        const int EPB = (EE + gridDim.x - 1) / gridDim.x;
        int e0 = blockIdx.x * EPB;
        int e1 = e0 + EPB < EE ? e0 + EPB : EE;
        for (int e = e0 + tid; e < e1; e += 256) {
            int src = ei[e];
            int dst = ei[EE + e];
            int pos = atomicAdd(&g_cur[dst], 1);
            g_csr_src[pos] = src;
        }
    }

    const uint32_t sb = smem_u32(smem);
    const uint32_t sAh = sb, sAl = sb + 32768, sWh = sb + 65536, sWl = sb + 98304;
    const int rowBase = blockIdx.x * 128;

    // ---- stage A (prebias + act, hi/lo split) ----
#pragma unroll
    for (int it = 0; it < 8; it++) {
        int idx = tid + it * 256;
        int r = idx >> 4, g = idx & 15;
        int row = rowBase + r;
        float v[8];
        if (row < M) {
            float4 u0 = *(const float4*)(A + (size_t)row * DD + g * 8);
            float4 u1 = *(const float4*)(A + (size_t)row * DD + g * 8 + 4);
            v[0] = u0.x; v[1] = u0.y; v[2] = u0.z; v[3] = u0.w;
            v[4] = u1.x; v[5] = u1.y; v[6] = u1.z; v[7] = u1.w;
        } else {
#pragma unroll
            for (int i = 0; i < 8; i++) v[i] = 0.f;
        }
        if (prebias != nullptr) {
#pragma unroll
            for (int i = 0; i < 8; i++) v[i] += prebias[g * 8 + i];
        }
#pragma unroll
        for (int i = 0; i < 8; i++) v[i] = lrelu(v[i], 0.01f);
        uint32_t hi[4], lo[4];
#pragma unroll
        for (int p = 0; p < 4; p++) {
            float a0 = v[2 * p], a1 = v[2 * p + 1];
            float h0 = __bfloat162float(__float2bfloat16(a0));
            float h1 = __bfloat162float(__float2bfloat16(a1));
            hi[p] = pack_bf2(h0, h1);
            lo[p] = pack_bf2(a0 - h0, a1 - h1);
        }
        int off = r * 256 + ((g ^ (r & 7)) << 4);
        *(uint4*)(smem + off) = make_uint4(hi[0], hi[1], hi[2], hi[3]);
        *(uint4*)(smem + 32768 + off) = make_uint4(lo[0], lo[1], lo[2], lo[3]);
    }
    // ---- stage W (hi/lo split) ----
#pragma unroll
    for (int it = 0; it < 8; it++) {
        int idx = tid + it * 256;
        int r = idx >> 4, g = idx & 15;
        float4 u0 = *(const float4*)(W + (size_t)r * DD + g * 8);
        float4 u1 = *(const float4*)(W + (size_t)r * DD + g * 8 + 4);
        float v[8] = {u0.x, u0.y, u0.z, u0.w, u1.x, u1.y, u1.z, u1.w};
        uint32_t hi[4], lo[4];
#pragma unroll
        for (int p = 0; p < 4; p++) {
            float a0 = v[2 * p], a1 = v[2 * p + 1];
            float h0 = __bfloat162float(__float2bfloat16(a0));
            float h1 = __bfloat162float(__float2bfloat16(a1));
            hi[p] = pack_bf2(h0, h1);
            lo[p] = pack_bf2(a0 - h0, a1 - h1);
        }
        int off = r * 256 + ((g ^ (r & 7)) << 4);
        *(uint4*)(smem + 65536 + off) = make_uint4(hi[0], hi[1], hi[2], hi[3]);
        *(uint4*)(smem + 98304 + off) = make_uint4(lo[0], lo[1], lo[2], lo[3]);
    }
    __syncthreads();

    const int wid = tid >> 5, lane = tid & 31;
    const int wm = (wid >> 2) * 64, wn = (wid & 3) * 32;

    float D[4][4][4];
#pragma unroll
    for (int mt = 0; mt < 4; mt++)
#pragma unroll
        for (int nt = 0; nt < 4; nt++)
#pragma unroll
            for (int k = 0; k < 4; k++) D[mt][nt][k] = 0.f;

    // ldmatrix lane addressing (canonical m16n8k16 row.col layouts)
    const int subA = lane >> 3;
    const int rA = (lane & 7) | ((subA & 1) << 3);  // row within 16
    const int gA = subA >> 1;                        // granule 0/1
    const int rB = lane & 7;                         // row within 8
    const int gB = (lane >> 3) & 1;

#pragma unroll
    for (int p = 0; p < 3; p++) {
        uint32_t aBase = (p == 2) ? sAl : sAh;
        uint32_t bBase = (p == 1) ? sWl : sWh;
#pragma unroll
        for (int ks = 0; ks < 8; ks++) {
            uint32_t a[4][4], b[4][2];
#pragma unroll
            for (int mt = 0; mt < 4; mt++) {
                int r = wm + mt * 16 + rA;
                int g = 2 * ks + gA;
                ldsm_x4(a[mt][0], a[mt][1], a[mt][2], a[mt][3],
                        aBase + r * 256 + ((g ^ (r & 7)) << 4));
            }
#pragma unroll
            for (int nt = 0; nt < 4; nt++) {
                int r = wn + nt * 8 + rB;
                int g = 2 * ks + gB;
                ldsm_x2(b[nt][0], b[nt][1],
                        bBase + r * 256 + ((g ^ (r & 7)) << 4));
            }
#pragma unroll
            for (int mt = 0; mt < 4; mt++)
#pragma unroll
                for (int nt = 0; nt < 4; nt++)
                    mma16816(D[mt][nt], a[mt], b[nt]);
        }
    }
    __syncthreads();  // done with tiles; smem reusable for attention reduce

    // ---- epilogue ----
    const int q = lane >> 2, c2 = (lane & 3) * 2;
    float bj0[4], bj1[4], as0[4], as1[4], ad0[4], ad1[4];
#pragma unroll
    for (int nt = 0; nt < 4; nt++) {
        int col = wn + nt * 8 + c2;
        bj0[nt] = (bias != nullptr) ? bias[col] : 0.f;
        bj1[nt] = (bias != nullptr) ? bias[col + 1] : 0.f;
        if (ATTN) {
            as0[nt] = attS[col]; as1[nt] = attS[col + 1];
            ad0[nt] = attD[col]; ad1[nt] = attD[col + 1];
        }
    }
    float* sp = (float*)smem;        // [128][16]
    float* sd = sp + 128 * 16;

#pragma unroll
    for (int mt = 0; mt < 4; mt++) {
#pragma unroll
        for (int half = 0; half < 2; half++) {
            int rl = wm + mt * 16 + q + half * 8;
            int row = rowBase + rl;
            bool ok = row < M;
#pragma unroll
            for (int nt = 0; nt < 4; nt++) {
                int col = wn + nt * 8 + c2;
                float v0 = D[mt][nt][half * 2] + bj0[nt];
                float v1 = D[mt][nt][half * 2 + 1] + bj1[nt];
                if (ATTN) {
                    if (ok) {
                        *(__half2*)(g_h16 + (size_t)row * DD + col) =
                            __floats2half2_rn(v0, v1);
                    }
                    float ps = v0 * as0[nt] + v1 * as1[nt];
                    float pd = v0 * ad0[nt] + v1 * ad1[nt];
                    ps += __shfl_xor_sync(0xffffffffu, ps, 1);
                    ps += __shfl_xor_sync(0xffffffffu, ps, 2);
                    pd += __shfl_xor_sync(0xffffffffu, pd, 1);
                    pd += __shfl_xor_sync(0xffffffffu, pd, 2);
                    if ((lane & 3) == 0) {
                        sp[rl * 16 + (wid & 3) * 4 + nt] = ps;
                        sd[rl * 16 + (wid & 3) * 4 + nt] = pd;
                    }
                } else if (ok) {
                    *(float2*)(out + (size_t)row * DD + col) =
                        make_float2(v0, v1);
                }
            }
        }
    }
    if (ATTN) {
        __syncthreads();
        if (tid < 128) {
            int row = rowBase + tid;
            if (row < M) {
#pragma unroll
                for (int h = 0; h < 4; h++) {
                    float s = sp[tid * 16 + h * 4 + 0] + sp[tid * 16 + h * 4 + 1]
                            + sp[tid * 16 + h * 4 + 2] + sp[tid * 16 + h * 4 + 3];
                    float d = sd[tid * 16 + h * 4 + 0] + sd[tid * 16 + h * 4 + 1]
                            + sd[tid * 16 + h * 4 + 2] + sd[tid * 16 + h * 4 + 3];
                    g_asrc[row * HH + h] = s;
                    g_adst[row * HH + h] = d;
                }
            }
        }
    }
}

// -------------------------- CSR scan --------------------------------------
__global__ void __launch_bounds__(1024) scan_kernel() {
    __shared__ int ssum[1024];
    const int t = threadIdx.x;
    const int CH = (NN + 1023) / 1024;
    const int base = t * CH;

    int s = 0;
#pragma unroll 4
    for (int i = 0; i < CH; i++) {
        int idx = base + i;
        if (idx < NN) s += g_cnt[idx];
    }
    ssum[t] = s;
    __syncthreads();
    for (int off = 1; off < 1024; off <<= 1) {
        int v = ssum[t];
        int add = (t >= off) ? ssum[t - off] : 0;
        __syncthreads();
        ssum[t] = v + add;
        __syncthreads();
    }
    int run = ssum[t] - s;
    for (int i = 0; i < CH; i++) {
        int idx = base + i;
        if (idx < NN) {
            g_off[idx] = run;
            g_cur[idx] = run;
            run += g_cnt[idx];
        }
    }
    if (t == 1023) g_off[NN] = EE;
}

// ---------------------------------------------------------------------------
// Fused softmax + aggregation: warp per dst; fp16 gathers. 4th launch ->
// gets the ncu capture. Zeroes g_cnt for next call.
// ---------------------------------------------------------------------------
__global__ void __launch_bounds__(256) agg_kernel() {
    int warp = (blockIdx.x * blockDim.x + threadIdx.x) >> 5;
    int lane = threadIdx.x & 31;
    if (warp >= NN) return;
    const int d = warp;
    const int head = lane >> 3;
    const int ph = lane & 3;
    const int pe = lane >> 2;
    const int beg = g_off[d], end = g_off[d + 1];
    const float adst_ph = g_adst[d * HH + ph];

    if (lane == 0) g_cnt[d] = 0;

    float4 acc = make_float4(0.f, 0.f, 0.f, 0.f);
    float den = 0.f;

    int base = beg;
    for (; base + 8 <= end; base += 8) {
        int srcl = g_csr_src[base + pe];
        float s = g_asrc[srcl * HH + ph] + adst_ph;
        float exv = __expf(lrelu(s, 0.2f));
#pragma unroll
        for (int j = 0; j < 8; j++) {
            float ex = __shfl_sync(0xffffffffu, exv, j * 4 + head);
            int sj = __shfl_sync(0xffffffffu, srcl, j * 4 + head);
            uint2 u = *(const uint2*)(g_h16 + (size_t)sj * DD + lane * 4);
            float2 f0 = __half22float2(*(__half2*)&u.x);
            float2 f1 = __half22float2(*(__half2*)&u.y);
            acc.x = fmaf(ex, f0.x, acc.x);
            acc.y = fmaf(ex, f0.y, acc.y);
            acc.z = fmaf(ex, f1.x, acc.z);
            acc.w = fmaf(ex, f1.y, acc.w);
            den += ex;
        }
    }
    if (base < end) {
        int eidx = base + pe;
        int srcl = 0;
        float exv = 0.f;
        if (eidx < end) {
            srcl = g_csr_src[eidx];
            float s = g_asrc[srcl * HH + ph] + adst_ph;
            exv = __expf(lrelu(s, 0.2f));
        }
        int nrem = end - base;
#pragma unroll
        for (int j = 0; j < 8; j++) {
            if (j >= nrem) break;
            float ex = __shfl_sync(0xffffffffu, exv, j * 4 + head);
            int sj = __shfl_sync(0xffffffffu, srcl, j * 4 + head);
            uint2 u = *(const uint2*)(g_h16 + (size_t)sj * DD + lane * 4);
            float2 f0 = __half22float2(*(__half2*)&u.x);
            float2 f1 = __half22float2(*(__half2*)&u.y);
            acc.x = fmaf(ex, f0.x, acc.x);
            acc.y = fmaf(ex, f0.y, acc.y);
            acc.z = fmaf(ex, f1.x, acc.z);
            acc.w = fmaf(ex, f1.y, acc.w);
            den += ex;
        }
    }
    float inv = 1.f / (den + 1e-16f);
    *(float4*)(g_agg + (size_t)d * DD + lane * 4) =
        make_float4(acc.x * inv, acc.y * inv, acc.z * inv, acc.w * inv);
}

// ---------------------------------------------------------------------------
extern "C" void kernel_launch(void* const* d_in, const int* in_sizes, int n_in,
                              void* d_out, int out_size) {
    const float* x       = (const float*)d_in[0];
    const int*   ei      = (const int*)d_in[1];
    // d_in[2] = edge_type (unused by forward)
    const float* W1      = (const float*)d_in[3];
    const float* b1      = (const float*)d_in[4];
    const float* Wg      = (const float*)d_in[5];
    const float* att_src = (const float*)d_in[6];
    const float* att_dst = (const float*)d_in[7];
    const float* bias_g  = (const float*)d_in[8];
    const float* W2      = (const float*)d_in[9];
    const float* b2      = (const float*)d_in[10];
    float* out = (float*)d_out;

    float *pagg, *pWf, *pbf;
    cudaGetSymbolAddress((void**)&pagg, g_agg);
    cudaGetSymbolAddress((void**)&pWf, g_Wf);
    cudaGetSymbolAddress((void**)&pbf, g_bf);

    const int SMEM = 4 * 32768;  // 128 KB: Ah, Al, Wh, Wl
    cudaFuncSetAttribute(gemm_kernel<true>,
                         cudaFuncAttributeMaxDynamicSharedMemorySize, SMEM);
    cudaFuncSetAttribute(gemm_kernel<false>,
                         cudaFuncAttributeMaxDynamicSharedMemorySize, SMEM);

    const int gblocks = (NN + 127) / 128;  // 782

    // 1: dst histogram + weight fusion
    hist_wf_kernel<<<HBLK + 64, 256>>>(ei, Wg, W1, b1);
    // 2: CSR offsets
    scan_kernel<<<1, 1024>>>();
    // 3: CSR scatter (prologue) + h16/attention-score GEMM
    gemm_kernel<true><<<gblocks, 256, SMEM>>>(x, pWf, nullptr, pbf,
                                              att_src, att_dst, nullptr, NN, ei);
    // 4: fused softmax + aggregation  (<- ncu captures 4th launch)
    agg_kernel<<<(NN * 32 + 255) / 256, 256>>>();
    // 5: out = leaky(agg + bias_g)@W2^T + b2
    gemm_kernel<false><<<gblocks, 256, SMEM>>>(pagg, W2, bias_g, b2,
                                               nullptr, nullptr, out, NN, nullptr);
}

// round 9
// speedup vs baseline: 3.1231x; 1.1697x over previous
#include <cuda_runtime.h>
#include <cuda_bf16.h>
#include <cuda_fp16.h>
#include <math.h>
#include <cstdint>

#define NN 100000
#define EE 1600000
#define DD 128
#define HH 4

// ---------------- device scratch (static globals: allocation-free rule) ----
__device__ __half g_h16[(size_t)NN * DD];   // fp16 h for agg gather
__device__ float  g_agg[(size_t)NN * DD];   // aggregated messages
__device__ float  g_bf[DD];                 // Wg @ b1
__device__ uint4  g_Wfh[2048], g_Wfl[2048]; // Wf=Wg@W1 bf16 hi/lo, smem-layout
__device__ uint4  g_W2h[2048], g_W2l[2048]; // W2 bf16 hi/lo, smem-layout
__device__ float  g_asrc[NN * HH];
__device__ float  g_adst[NN * HH];
__device__ int    g_cnt[NN];                // per-dst degree (zeroed by agg)
__device__ int    g_off[NN + 1];            // CSR offsets
__device__ int    g_cur[NN];                // scatter cursors
__device__ int    g_csr_src[EE];            // src per edge, bucketed by dst

__device__ __forceinline__ float lrelu(float x, float s) {
    return x >= 0.f ? x : s * x;
}
__device__ __forceinline__ uint32_t smem_u32(const void* p) {
    uint32_t a;
    asm("{ .reg .u64 t; cvta.to.shared.u64 t, %1; cvt.u32.u64 %0, t; }"
        : "=r"(a) : "l"(p));
    return a;
}
__device__ __forceinline__ uint32_t pack_bf2(float a, float b) {
    __nv_bfloat162 t = __floats2bfloat162_rn(a, b);
    return *reinterpret_cast<uint32_t*>(&t);
}
__device__ __forceinline__ void ldsm_x4(uint32_t& r0, uint32_t& r1,
                                        uint32_t& r2, uint32_t& r3, uint32_t a) {
    asm volatile("ldmatrix.sync.aligned.m8n8.x4.shared.b16 {%0,%1,%2,%3}, [%4];"
                 : "=r"(r0), "=r"(r1), "=r"(r2), "=r"(r3) : "r"(a));
}
__device__ __forceinline__ void ldsm_x2(uint32_t& r0, uint32_t& r1, uint32_t a) {
    asm volatile("ldmatrix.sync.aligned.m8n8.x2.shared.b16 {%0,%1}, [%2];"
                 : "=r"(r0), "=r"(r1) : "r"(a));
}
__device__ __forceinline__ void mma16816(float* d, const uint32_t* a,
                                         const uint32_t* b) {
    asm volatile("mma.sync.aligned.m16n8k16.row.col.f32.bf16.bf16.f32 "
                 "{%0,%1,%2,%3}, {%4,%5,%6,%7}, {%8,%9}, {%0,%1,%2,%3};"
                 : "+f"(d[0]), "+f"(d[1]), "+f"(d[2]), "+f"(d[3])
                 : "r"(a[0]), "r"(a[1]), "r"(a[2]), "r"(a[3]),
                   "r"(b[0]), "r"(b[1]));
}

// ---------------------------------------------------------------------------
// Fused setup grid: [0,HBLK) dst histogram; [HBLK,HBLK+64) Wf=Wg@W1 rows
// (+ bf16 hi/lo split into smem layout); [HBLK+64,HBLK+72) W2 bf16 split.
// smem tile layout: row r (256B), 16B granule g at r*256 + ((g^(r&7))<<4).
// ---------------------------------------------------------------------------
#define HBLK ((EE + 255) / 256)
__global__ void __launch_bounds__(256) hist_wf_kernel(
    const int* __restrict__ ei, const float* __restrict__ Wg,
    const float* __restrict__ W1, const float* __restrict__ b1,
    const float* __restrict__ W2)
{
    if (blockIdx.x < HBLK) {
        int e = blockIdx.x * 256 + threadIdx.x;
        if (e < EE) atomicAdd(&g_cnt[ei[EE + e]], 1);
    } else if (blockIdx.x < HBLK + 64) {
        int i = (blockIdx.x - HBLK) * 2 + (threadIdx.x >> 7);  // row
        int k = threadIdx.x & 127;                              // col
        float acc = 0.f, accb = 0.f;
#pragma unroll 8
        for (int j = 0; j < DD; j++) {
            float w = Wg[i * DD + j];
            acc = fmaf(w, W1[j * DD + k], acc);
            accb = fmaf(w, b1[j], accb);
        }
        float h = __bfloat162float(__float2bfloat16(acc));
        int off = i * 256 + ((((k >> 3) ^ (i & 7))) << 4) + (k & 7) * 2;
        *(__nv_bfloat16*)((char*)g_Wfh + off) = __float2bfloat16(acc);
        *(__nv_bfloat16*)((char*)g_Wfl + off) = __float2bfloat16(acc - h);
        if (k == 0) g_bf[i] = accb;
    } else {
        int gidx = (blockIdx.x - HBLK - 64) * 256 + threadIdx.x;  // 0..2047
        int r = gidx >> 4, g = gidx & 15;
        float4 u0 = *(const float4*)(W2 + (size_t)r * DD + g * 8);
        float4 u1 = *(const float4*)(W2 + (size_t)r * DD + g * 8 + 4);
        float v[8] = {u0.x, u0.y, u0.z, u0.w, u1.x, u1.y, u1.z, u1.w};
        uint32_t hi[4], lo[4];
#pragma unroll
        for (int p = 0; p < 4; p++) {
            float a0 = v[2 * p], a1 = v[2 * p + 1];
            float h0 = __bfloat162float(__float2bfloat16(a0));
            float h1 = __bfloat162float(__float2bfloat16(a1));
            hi[p] = pack_bf2(h0, h1);
            lo[p] = pack_bf2(a0 - h0, a1 - h1);
        }
        int off = r * 256 + (((g ^ (r & 7))) << 4);
        *(uint4*)((char*)g_W2h + off) = make_uint4(hi[0], hi[1], hi[2], hi[3]);
        *(uint4*)((char*)g_W2l + off) = make_uint4(lo[0], lo[1], lo[2], lo[3]);
    }
}

// ---------------------------------------------------------------------------
// HMMA GEMM (512 thr): out[M,128] = leaky(A + prebias, 0.01) @ W^T + bias
// A split bf16 hi/lo in-kernel; W hi/lo tiles pre-swizzled in global (straight
// uint4 copy into smem). D = AhWh + AhWl + AlWh, fp32 accumulate.
// Warp grid 4(m)x4(n); per warp 2x4 m16n8 tiles; K in 8 k16 steps.
// ATTN: CSR-scatter prologue; epilogue writes fp16 h mirror + attn scores.
// ---------------------------------------------------------------------------
template <bool ATTN>
__global__ void __launch_bounds__(512, 1) gemm_kernel(
    const float* __restrict__ A,
    const uint4* __restrict__ Wh, const uint4* __restrict__ Wl,
    const float* __restrict__ prebias, const float* __restrict__ bias,
    const float* __restrict__ attS, const float* __restrict__ attD,
    float* __restrict__ out, int M, const int* __restrict__ ei)
{
    extern __shared__ char smem[];
    const int tid = threadIdx.x;

    if (ATTN) {  // fused CSR scatter (independent work)
        const int EPB = (EE + gridDim.x - 1) / gridDim.x;
        int e0 = blockIdx.x * EPB;
        int e1 = e0 + EPB < EE ? e0 + EPB : EE;
        for (int e = e0 + tid; e < e1; e += 512) {
            int src = ei[e];
            int dst = ei[EE + e];
            int pos = atomicAdd(&g_cur[dst], 1);
            g_csr_src[pos] = src;
        }
    }

    const uint32_t sb = smem_u32(smem);
    const uint32_t sAh = sb, sAl = sb + 32768, sWh = sb + 65536, sWl = sb + 98304;
    const int rowBase = blockIdx.x * 128;

    // ---- W tiles: straight copy (pre-swizzled in global, L2-resident) ----
#pragma unroll
    for (int it = 0; it < 4; it++) {
        int idx = tid + it * 512;  // 0..2047
        ((uint4*)(smem + 65536))[idx] = Wh[idx];
        ((uint4*)(smem + 98304))[idx] = Wl[idx];
    }
    // ---- A tile: load fp32, act, hi/lo split ----
#pragma unroll
    for (int it = 0; it < 4; it++) {
        int idx = tid + it * 512;  // granule index 0..2047
        int r = idx >> 4, g = idx & 15;
        int row = rowBase + r;
        float v[8];
        if (row < M) {
            float4 u0 = *(const float4*)(A + (size_t)row * DD + g * 8);
            float4 u1 = *(const float4*)(A + (size_t)row * DD + g * 8 + 4);
            v[0] = u0.x; v[1] = u0.y; v[2] = u0.z; v[3] = u0.w;
            v[4] = u1.x; v[5] = u1.y; v[6] = u1.z; v[7] = u1.w;
        } else {
#pragma unroll
            for (int i = 0; i < 8; i++) v[i] = 0.f;
        }
        if (prebias != nullptr) {
#pragma unroll
            for (int i = 0; i < 8; i++) v[i] += prebias[g * 8 + i];
        }
#pragma unroll
        for (int i = 0; i < 8; i++) v[i] = lrelu(v[i], 0.01f);
        uint32_t hi[4], lo[4];
#pragma unroll
        for (int p = 0; p < 4; p++) {
            float a0 = v[2 * p], a1 = v[2 * p + 1];
            float h0 = __bfloat162float(__float2bfloat16(a0));
            float h1 = __bfloat162float(__float2bfloat16(a1));
            hi[p] = pack_bf2(h0, h1);
            lo[p] = pack_bf2(a0 - h0, a1 - h1);
        }
        int off = r * 256 + ((g ^ (r & 7)) << 4);
        *(uint4*)(smem + off) = make_uint4(hi[0], hi[1], hi[2], hi[3]);
        *(uint4*)(smem + 32768 + off) = make_uint4(lo[0], lo[1], lo[2], lo[3]);
    }
    __syncthreads();

    const int wid = tid >> 5, lane = tid & 31;
    const int wm = (wid >> 2) * 32, wn = (wid & 3) * 32;

    float D[2][4][4];
#pragma unroll
    for (int mt = 0; mt < 2; mt++)
#pragma unroll
        for (int nt = 0; nt < 4; nt++)
#pragma unroll
            for (int k = 0; k < 4; k++) D[mt][nt][k] = 0.f;

    const int subA = lane >> 3;
    const int rA = (lane & 7) | ((subA & 1) << 3);
    const int gA = subA >> 1;
    const int rB = lane & 7;
    const int gB = (lane >> 3) & 1;

#pragma unroll
    for (int p = 0; p < 3; p++) {
        uint32_t aBase = (p == 2) ? sAl : sAh;
        uint32_t bBase = (p == 1) ? sWl : sWh;
#pragma unroll
        for (int ks = 0; ks < 8; ks++) {
            uint32_t a[2][4], b[4][2];
#pragma unroll
            for (int mt = 0; mt < 2; mt++) {
                int r = wm + mt * 16 + rA;
                int g = 2 * ks + gA;
                ldsm_x4(a[mt][0], a[mt][1], a[mt][2], a[mt][3],
                        aBase + r * 256 + ((g ^ (r & 7)) << 4));
            }
#pragma unroll
            for (int nt = 0; nt < 4; nt++) {
                int r = wn + nt * 8 + rB;
                int g = 2 * ks + gB;
                ldsm_x2(b[nt][0], b[nt][1],
                        bBase + r * 256 + ((g ^ (r & 7)) << 4));
            }
#pragma unroll
            for (int mt = 0; mt < 2; mt++)
#pragma unroll
                for (int nt = 0; nt < 4; nt++)
                    mma16816(D[mt][nt], a[mt], b[nt]);
        }
    }
    __syncthreads();  // tiles done; smem reusable for attention reduce

    // ---- epilogue ----
    const int q = lane >> 2, c2 = (lane & 3) * 2;
    float bj0[4], bj1[4], as0[4], as1[4], ad0[4], ad1[4];
#pragma unroll
    for (int nt = 0; nt < 4; nt++) {
        int col = wn + nt * 8 + c2;
        bj0[nt] = (bias != nullptr) ? bias[col] : 0.f;
        bj1[nt] = (bias != nullptr) ? bias[col + 1] : 0.f;
        if (ATTN) {
            as0[nt] = attS[col]; as1[nt] = attS[col + 1];
            ad0[nt] = attD[col]; ad1[nt] = attD[col + 1];
        }
    }
    float* sp = (float*)smem;        // [128][16]
    float* sd = sp + 128 * 16;

#pragma unroll
    for (int mt = 0; mt < 2; mt++) {
#pragma unroll
        for (int half = 0; half < 2; half++) {
            int rl = wm + mt * 16 + q + half * 8;
            int row = rowBase + rl;
            bool ok = row < M;
#pragma unroll
            for (int nt = 0; nt < 4; nt++) {
                int col = wn + nt * 8 + c2;
                float v0 = D[mt][nt][half * 2] + bj0[nt];
                float v1 = D[mt][nt][half * 2 + 1] + bj1[nt];
                if (ATTN) {
                    if (ok) {
                        *(__half2*)(g_h16 + (size_t)row * DD + col) =
                            __floats2half2_rn(v0, v1);
                    }
                    float ps = v0 * as0[nt] + v1 * as1[nt];
                    float pd = v0 * ad0[nt] + v1 * ad1[nt];
                    ps += __shfl_xor_sync(0xffffffffu, ps, 1);
                    ps += __shfl_xor_sync(0xffffffffu, ps, 2);
                    pd += __shfl_xor_sync(0xffffffffu, pd, 1);
                    pd += __shfl_xor_sync(0xffffffffu, pd, 2);
                    if ((lane & 3) == 0) {
                        sp[rl * 16 + (wid & 3) * 4 + nt] = ps;
                        sd[rl * 16 + (wid & 3) * 4 + nt] = pd;
                    }
                } else if (ok) {
                    *(float2*)(out + (size_t)row * DD + col) =
                        make_float2(v0, v1);
                }
            }
        }
    }
    if (ATTN) {
        __syncthreads();
        if (tid < 128) {
            int row = rowBase + tid;
            if (row < M) {
#pragma unroll
                for (int h = 0; h < 4; h++) {
                    float s = sp[tid * 16 + h * 4 + 0] + sp[tid * 16 + h * 4 + 1]
                            + sp[tid * 16 + h * 4 + 2] + sp[tid * 16 + h * 4 + 3];
                    float d = sd[tid * 16 + h * 4 + 0] + sd[tid * 16 + h * 4 + 1]
                            + sd[tid * 16 + h * 4 + 2] + sd[tid * 16 + h * 4 + 3];
                    g_asrc[row * HH + h] = s;
                    g_adst[row * HH + h] = d;
                }
            }
        }
    }
}

// -------------------------- CSR scan + cursor copy ------------------------
__global__ void __launch_bounds__(1024) scan_kernel() {
    __shared__ int ssum[1024];
    const int t = threadIdx.x;
    const int CH = (NN + 1023) / 1024;
    const int base = t * CH;

    int s = 0;
#pragma unroll 4
    for (int i = 0; i < CH; i++) {
        int idx = base + i;
        if (idx < NN) s += g_cnt[idx];
    }
    ssum[t] = s;
    __syncthreads();
    for (int off = 1; off < 1024; off <<= 1) {
        int v = ssum[t];
        int add = (t >= off) ? ssum[t - off] : 0;
        __syncthreads();
        ssum[t] = v + add;
        __syncthreads();
    }
    int run = ssum[t] - s;
    for (int i = 0; i < CH; i++) {
        int idx = base + i;
        if (idx < NN) {
            g_off[idx] = run;
            run += g_cnt[idx];
        }
    }
    if (t == 1023) g_off[NN] = EE;
}

__global__ void __launch_bounds__(256) cur_copy_kernel() {
    int idx = blockIdx.x * 256 + threadIdx.x;
    if (idx < NN) g_cur[idx] = g_off[idx];
}

// ---------------------------------------------------------------------------
// Fused softmax + aggregation: warp per dst; fp16 gathers. Zeroes g_cnt.
// ---------------------------------------------------------------------------
__global__ void __launch_bounds__(256) agg_kernel() {
    int warp = (blockIdx.x * blockDim.x + threadIdx.x) >> 5;
    int lane = threadIdx.x & 31;
    if (warp >= NN) return;
    const int d = warp;
    const int head = lane >> 3;
    const int ph = lane & 3;
    const int pe = lane >> 2;
    const int beg = g_off[d], end = g_off[d + 1];
    const float adst_ph = g_adst[d * HH + ph];

    if (lane == 0) g_cnt[d] = 0;

    float4 acc = make_float4(0.f, 0.f, 0.f, 0.f);
    float den = 0.f;

    int base = beg;
    for (; base + 8 <= end; base += 8) {
        int srcl = g_csr_src[base + pe];
        float s = g_asrc[srcl * HH + ph] + adst_ph;
        float exv = __expf(lrelu(s, 0.2f));
#pragma unroll
        for (int j = 0; j < 8; j++) {
            float ex = __shfl_sync(0xffffffffu, exv, j * 4 + head);
            int sj = __shfl_sync(0xffffffffu, srcl, j * 4 + head);
            uint2 u = *(const uint2*)(g_h16 + (size_t)sj * DD + lane * 4);
            float2 f0 = __half22float2(*(__half2*)&u.x);
            float2 f1 = __half22float2(*(__half2*)&u.y);
            acc.x = fmaf(ex, f0.x, acc.x);
            acc.y = fmaf(ex, f0.y, acc.y);
            acc.z = fmaf(ex, f1.x, acc.z);
            acc.w = fmaf(ex, f1.y, acc.w);
            den += ex;
        }
    }
    if (base < end) {
        int eidx = base + pe;
        int srcl = 0;
        float exv = 0.f;
        if (eidx < end) {
            srcl = g_csr_src[eidx];
            float s = g_asrc[srcl * HH + ph] + adst_ph;
            exv = __expf(lrelu(s, 0.2f));
        }
        int nrem = end - base;
#pragma unroll
        for (int j = 0; j < 8; j++) {
            if (j >= nrem) break;
            float ex = __shfl_sync(0xffffffffu, exv, j * 4 + head);
            int sj = __shfl_sync(0xffffffffu, srcl, j * 4 + head);
            uint2 u = *(const uint2*)(g_h16 + (size_t)sj * DD + lane * 4);
            float2 f0 = __half22float2(*(__half2*)&u.x);
            float2 f1 = __half22float2(*(__half2*)&u.y);
            acc.x = fmaf(ex, f0.x, acc.x);
            acc.y = fmaf(ex, f0.y, acc.y);
            acc.z = fmaf(ex, f1.x, acc.z);
            acc.w = fmaf(ex, f1.y, acc.w);
            den += ex;
        }
    }
    float inv = 1.f / (den + 1e-16f);
    *(float4*)(g_agg + (size_t)d * DD + lane * 4) =
        make_float4(acc.x * inv, acc.y * inv, acc.z * inv, acc.w * inv);
}

// ---------------------------------------------------------------------------
extern "C" void kernel_launch(void* const* d_in, const int* in_sizes, int n_in,
                              void* d_out, int out_size) {
    const float* x       = (const float*)d_in[0];
    const int*   ei      = (const int*)d_in[1];
    // d_in[2] = edge_type (unused by forward)
    const float* W1      = (const float*)d_in[3];
    const float* b1      = (const float*)d_in[4];
    const float* Wg      = (const float*)d_in[5];
    const float* att_src = (const float*)d_in[6];
    const float* att_dst = (const float*)d_in[7];
    const float* bias_g  = (const float*)d_in[8];
    const float* W2      = (const float*)d_in[9];
    const float* b2      = (const float*)d_in[10];
    float* out = (float*)d_out;

    float *pagg, *pbf;
    uint4 *pWfh, *pWfl, *pW2h, *pW2l;
    cudaGetSymbolAddress((void**)&pagg, g_agg);
    cudaGetSymbolAddress((void**)&pbf, g_bf);
    cudaGetSymbolAddress((void**)&pWfh, g_Wfh);
    cudaGetSymbolAddress((void**)&pWfl, g_Wfl);
    cudaGetSymbolAddress((void**)&pW2h, g_W2h);
    cudaGetSymbolAddress((void**)&pW2l, g_W2l);

    const int SMEM = 4 * 32768;  // 128 KB: Ah, Al, Wh, Wl
    cudaFuncSetAttribute(gemm_kernel<true>,
                         cudaFuncAttributeMaxDynamicSharedMemorySize, SMEM);
    cudaFuncSetAttribute(gemm_kernel<false>,
                         cudaFuncAttributeMaxDynamicSharedMemorySize, SMEM);

    const int gblocks = (NN + 127) / 128;  // 782

    // 1: dst histogram + Wf compute/split + W2 split
    hist_wf_kernel<<<HBLK + 64 + 8, 256>>>(ei, Wg, W1, b1, W2);
    // 2: CSR offsets
    scan_kernel<<<1, 1024>>>();
    // 3: cursor copy
    cur_copy_kernel<<<(NN + 255) / 256, 256>>>();
    // 4: CSR scatter + h16/attention-score GEMM  (<- ncu captures 4th launch)
    gemm_kernel<true><<<gblocks, 512, SMEM>>>(x, pWfh, pWfl, nullptr, pbf,
                                              att_src, att_dst, nullptr, NN, ei);
    // 5: fused softmax + aggregation
    agg_kernel<<<(NN * 32 + 255) / 256, 256>>>();
    // 6: out = leaky(agg + bias_g)@W2^T + b2
    gemm_kernel<false><<<gblocks, 512, SMEM>>>(pagg, pW2h, pW2l, bias_g, b2,
                                               nullptr, nullptr, out, NN, nullptr);
}